// round 4
// baseline (speedup 1.0000x reference)
#include <cuda_runtime.h>
#include <math.h>
#include <stdint.h>

// ---------------- problem constants ----------------
#define R_RAYS   4096
#define NSAMP    64
#define NPTS     (R_RAYS * NSAMP)   // 262144
#define D_HID    256
#define DHD      128
#define PE_P     63
#define PE_PAD   64
#define PE_D     27
#define NEAR_F   2.0f
#define FAR_F    6.0f

// ---------------- device scratch (static, allowed) ----------------
__device__ float g_pe[(size_t)NPTS * PE_PAD];    // 64 MiB
__device__ float g_hA[(size_t)NPTS * D_HID];     // 256 MiB
__device__ float g_hB[(size_t)NPTS * D_HID];     // 256 MiB
__device__ float g_hd[(size_t)NPTS * DHD];       // 128 MiB
__device__ float g_density[NPTS];
__device__ float g_rgb[NPTS * 3];
__device__ float g_vd[R_RAYS * 3];
__device__ float g_de[R_RAYS * PE_D];
__device__ float g_det[R_RAYS * DHD];
__device__ float g_W1p[PE_PAD * D_HID];

// ---------------- small prep kernels ----------------

// Pad W1 [63,256] -> [64,256] with zero last row.
__global__ void pad_w1_kernel(const float* __restrict__ W1) {
    int idx = blockIdx.x * blockDim.x + threadIdx.x;   // 0..16383
    g_W1p[idx] = (idx < PE_P * D_HID) ? W1[idx] : 0.0f;
}

// Per-ray: normalize viewdir, compute dir posenc (L=4 -> 27 vals).
__global__ void prep_rays_kernel(const float* __restrict__ viewdirs) {
    int r = blockIdx.x * blockDim.x + threadIdx.x;
    if (r >= R_RAYS) return;
    float vx = viewdirs[r * 3 + 0];
    float vy = viewdirs[r * 3 + 1];
    float vz = viewdirs[r * 3 + 2];
    float inv = 1.0f / sqrtf(vx * vx + vy * vy + vz * vz);
    vx *= inv; vy *= inv; vz *= inv;
    g_vd[r * 3 + 0] = vx; g_vd[r * 3 + 1] = vy; g_vd[r * 3 + 2] = vz;
    float* de = g_de + (size_t)r * PE_D;
    de[0] = vx; de[1] = vy; de[2] = vz;
    float v[3] = {vx, vy, vz};
    float f = 1.0f;
#pragma unroll
    for (int l = 0; l < 4; ++l) {
#pragma unroll
        for (int c = 0; c < 3; ++c) {
            float sn, cs;
            sincosf(v[c] * f, &sn, &cs);
            de[3 + l * 6 + c]     = sn;
            de[3 + l * 6 + 3 + c] = cs;
        }
        f *= 2.0f;
    }
}

// Per point: compute sample position + positional encoding (L=10 -> 63 vals, pad to 64).
// One block per ray, 64 threads = 64 samples.
__global__ void prep_pe_kernel(const float* __restrict__ xyz) {
    int ray = blockIdx.x;
    int s   = threadIdx.x;
    float ox = xyz[ray * 3 + 0], oy = xyz[ray * 3 + 1], oz = xyz[ray * 3 + 2];
    float dx = g_vd[ray * 3 + 0], dy = g_vd[ray * 3 + 1], dz = g_vd[ray * 3 + 2];
    float t  = (float)s * (1.0f / 63.0f);
    float sm = NEAR_F * (1.0f - t) + FAR_F * t;
    float p[3] = { fmaf(sm, dx, ox), fmaf(sm, dy, oy), fmaf(sm, dz, oz) };
    float* out = g_pe + (size_t)(ray * NSAMP + s) * PE_PAD;
    out[0] = p[0]; out[1] = p[1]; out[2] = p[2];
    float f = 1.0f;
#pragma unroll
    for (int l = 0; l < 10; ++l) {
#pragma unroll
        for (int c = 0; c < 3; ++c) {
            float sn, cs;
            sincosf(p[c] * f, &sn, &cs);
            out[3 + l * 6 + c]     = sn;
            out[3 + l * 6 + 3 + c] = cs;
        }
        f *= 2.0f;
    }
    out[63] = 0.0f;
}

// de_term[r, n] = sum_k de[r,k] * Wdir[256+k, n]   (the concat tail of the dir layer)
__global__ void de_term_kernel(const float* __restrict__ Wdir) {
    int t = blockIdx.x * blockDim.x + threadIdx.x;   // R_RAYS*DHD threads
    int r = t >> 7;
    int n = t & 127;
    const float* de = g_de + (size_t)r * PE_D;
    float s = 0.0f;
#pragma unroll
    for (int k = 0; k < PE_D; ++k)
        s = fmaf(de[k], Wdir[(size_t)(D_HID + k) * DHD + n], s);
    g_det[(size_t)r * DHD + n] = s;
}

// ---------------- tiled fp32 GEMM: C = act(A[M,lda] @ B[K,N] + bias + rowbias) ----------------
// BM=BN=128, BK=16, 256 threads, 8x8 per thread. M, N, K all multiples of tile dims.
template <bool RELU, bool ROWBIAS>
__global__ void __launch_bounds__(256)
sgemm_kernel(const float* __restrict__ A, int lda,
             const float* __restrict__ B,
             const float* __restrict__ bias,
             const float* __restrict__ rowbias,   // [R_RAYS, N], indexed by row>>6
             float* __restrict__ C, int N, int K)
{
    __shared__ float As[16][128];
    __shared__ float Bs[16][128];
    const int  tid = threadIdx.x;
    const long m0  = (long)blockIdx.x * 128;
    const int  n0  = blockIdx.y * 128;
    const int  aRow = tid >> 2;          // 0..63
    const int  aCol = (tid & 3) << 2;    // 0,4,8,12
    const int  bRow = tid >> 5;          // 0..7
    const int  bCol = (tid & 31) << 2;   // 0..124
    const int  ty = tid >> 4, tx = tid & 15;

    float acc[8][8];
#pragma unroll
    for (int i = 0; i < 8; ++i)
#pragma unroll
        for (int j = 0; j < 8; ++j) acc[i][j] = 0.0f;

    for (int k0 = 0; k0 < K; k0 += 16) {
#pragma unroll
        for (int r = 0; r < 2; ++r) {
            int row = aRow + r * 64;
            float4 v = *reinterpret_cast<const float4*>(A + (m0 + row) * (long)lda + k0 + aCol);
            As[aCol + 0][row] = v.x;
            As[aCol + 1][row] = v.y;
            As[aCol + 2][row] = v.z;
            As[aCol + 3][row] = v.w;
        }
#pragma unroll
        for (int r = 0; r < 2; ++r) {
            int krow = bRow + r * 8;
            *reinterpret_cast<float4*>(&Bs[krow][bCol]) =
                *reinterpret_cast<const float4*>(B + (long)(k0 + krow) * N + n0 + bCol);
        }
        __syncthreads();
#pragma unroll
        for (int kk = 0; kk < 16; ++kk) {
            float ra[8], rb[8];
            *(float4*)(ra)     = *(const float4*)&As[kk][ty * 8];
            *(float4*)(ra + 4) = *(const float4*)&As[kk][ty * 8 + 4];
            *(float4*)(rb)     = *(const float4*)&Bs[kk][tx * 8];
            *(float4*)(rb + 4) = *(const float4*)&Bs[kk][tx * 8 + 4];
#pragma unroll
            for (int i = 0; i < 8; ++i)
#pragma unroll
                for (int j = 0; j < 8; ++j)
                    acc[i][j] = fmaf(ra[i], rb[j], acc[i][j]);
        }
        __syncthreads();
    }

#pragma unroll
    for (int i = 0; i < 8; ++i) {
        long row = m0 + ty * 8 + i;
        const float* rbp = ROWBIAS ? (rowbias + (row >> 6) * (long)N) : nullptr;
#pragma unroll
        for (int jv = 0; jv < 2; ++jv) {
            int col = n0 + tx * 8 + jv * 4;
            float o[4];
#pragma unroll
            for (int q = 0; q < 4; ++q) {
                float v = acc[i][jv * 4 + q] + bias[col + q];
                if (ROWBIAS) v += rbp[col + q];
                if (RELU)    v = fmaxf(v, 0.0f);
                o[q] = v;
            }
            *reinterpret_cast<float4*>(C + row * (long)N + col) =
                make_float4(o[0], o[1], o[2], o[3]);
        }
    }
}

// ---------------- heads ----------------

__device__ __forceinline__ float warp_sum(float v) {
#pragma unroll
    for (int off = 16; off > 0; off >>= 1)
        v += __shfl_down_sync(0xffffffffu, v, off);
    return v;
}

// density[p] = h[p,:] . Wsig + bsig   (one warp per point)
__global__ void density_kernel(const float* __restrict__ h,
                               const float* __restrict__ Wsig,
                               const float* __restrict__ bsig) {
    int gw   = (blockIdx.x * blockDim.x + threadIdx.x) >> 5;
    int lane = threadIdx.x & 31;
    const float* hp = h + (size_t)gw * D_HID;
    float s = 0.0f;
#pragma unroll
    for (int i = 0; i < 8; ++i) {
        int k = lane + i * 32;
        s = fmaf(hp[k], Wsig[k], s);
    }
    s = warp_sum(s);
    if (lane == 0) g_density[gw] = s + bsig[0];
}

// rgb[p,:] = sigmoid(hd[p,:] @ Wrgb + brgb)   (one warp per point)
__global__ void rgb_kernel(const float* __restrict__ Wrgb,
                           const float* __restrict__ brgb) {
    int gw   = (blockIdx.x * blockDim.x + threadIdx.x) >> 5;
    int lane = threadIdx.x & 31;
    const float4 h = *reinterpret_cast<const float4*>(g_hd + (size_t)gw * DHD + lane * 4);
    int k = lane * 4;
    float a0, a1, a2;
    a0 = h.x * Wrgb[(k + 0) * 3 + 0] + h.y * Wrgb[(k + 1) * 3 + 0]
       + h.z * Wrgb[(k + 2) * 3 + 0] + h.w * Wrgb[(k + 3) * 3 + 0];
    a1 = h.x * Wrgb[(k + 0) * 3 + 1] + h.y * Wrgb[(k + 1) * 3 + 1]
       + h.z * Wrgb[(k + 2) * 3 + 1] + h.w * Wrgb[(k + 3) * 3 + 1];
    a2 = h.x * Wrgb[(k + 0) * 3 + 2] + h.y * Wrgb[(k + 1) * 3 + 2]
       + h.z * Wrgb[(k + 2) * 3 + 2] + h.w * Wrgb[(k + 3) * 3 + 2];
    a0 = warp_sum(a0); a1 = warp_sum(a1); a2 = warp_sum(a2);
    if (lane == 0) {
        g_rgb[gw * 3 + 0] = 1.0f / (1.0f + expf(-(a0 + brgb[0])));
        g_rgb[gw * 3 + 1] = 1.0f / (1.0f + expf(-(a1 + brgb[1])));
        g_rgb[gw * 3 + 2] = 1.0f / (1.0f + expf(-(a2 + brgb[2])));
    }
}

// ---------------- volume rendering (one thread per ray) ----------------
__global__ void render_kernel(float* __restrict__ out) {
    int ray = blockIdx.x * blockDim.x + threadIdx.x;
    if (ray >= R_RAYS) return;
    float T = 1.0f, r0 = 0.0f, r1 = 0.0f, r2 = 0.0f, depth = 0.0f, asum = 0.0f;
    for (int i = 0; i < NSAMP; ++i) {
        int p = ray * NSAMP + i;
        float ti = (float)i * (1.0f / 63.0f);
        float sm = NEAR_F * (1.0f - ti) + FAR_F * ti;
        float delta;
        if (i < NSAMP - 1) {
            float tn = (float)(i + 1) * (1.0f / 63.0f);
            delta = (NEAR_F * (1.0f - tn) + FAR_F * tn) - sm;
        } else {
            delta = 1e10f;
        }
        float sigma = fmaxf(g_density[p], 0.0f);
        float alpha = 1.0f - expf(-sigma * delta);
        float w = T * alpha;
        r0 += w * g_rgb[p * 3 + 0];
        r1 += w * g_rgb[p * 3 + 1];
        r2 += w * g_rgb[p * 3 + 2];
        depth += w * sm;
        asum  += w;
        T *= (1.0f - alpha);
    }
    float bk = 1.0f - asum;
    out[ray * 3 + 0] = r0 + bk;
    out[ray * 3 + 1] = r1 + bk;
    out[ray * 3 + 2] = r2 + bk;
    out[R_RAYS * 3 + ray] = depth;   // depth_map
    out[R_RAYS * 4 + ray] = asum;    // alpha_map
}

// ---------------- host launch ----------------
extern "C" void kernel_launch(void* const* d_in, const int* in_sizes, int n_in,
                              void* d_out, int out_size) {
    const float* xyz      = (const float*)d_in[0];
    const float* viewdirs = (const float*)d_in[1];
    const float* W1   = (const float*)d_in[2];
    const float* b1   = (const float*)d_in[3];
    const float* W2   = (const float*)d_in[4];
    const float* b2   = (const float*)d_in[5];
    const float* W3   = (const float*)d_in[6];
    const float* b3   = (const float*)d_in[7];
    const float* Wsig = (const float*)d_in[8];
    const float* bsig = (const float*)d_in[9];
    const float* Wfeat= (const float*)d_in[10];
    const float* bfeat= (const float*)d_in[11];
    const float* Wdir = (const float*)d_in[12];
    const float* bdir = (const float*)d_in[13];
    const float* Wrgb = (const float*)d_in[14];
    const float* brgb = (const float*)d_in[15];
    float* out = (float*)d_out;

    float *pe, *hA, *hB, *hd, *det, *w1p;
    cudaGetSymbolAddress((void**)&pe,  g_pe);
    cudaGetSymbolAddress((void**)&hA,  g_hA);
    cudaGetSymbolAddress((void**)&hB,  g_hB);
    cudaGetSymbolAddress((void**)&hd,  g_hd);
    cudaGetSymbolAddress((void**)&det, g_det);
    cudaGetSymbolAddress((void**)&w1p, g_W1p);

    // prep
    pad_w1_kernel<<<PE_PAD * D_HID / 256, 256>>>(W1);
    prep_rays_kernel<<<R_RAYS / 256, 256>>>(viewdirs);
    prep_pe_kernel<<<R_RAYS, NSAMP>>>(xyz);
    de_term_kernel<<<R_RAYS * DHD / 256, 256>>>(Wdir);

    const int gM = NPTS / 128;   // 2048
    // L1: pe[*,64] @ W1p[64,256] + b1, relu -> hA
    sgemm_kernel<true,  false><<<dim3(gM, 2), 256>>>(pe, PE_PAD, w1p, b1, nullptr, hA, D_HID, PE_PAD);
    // L2: hA @ W2 + b2, relu -> hB
    sgemm_kernel<true,  false><<<dim3(gM, 2), 256>>>(hA, D_HID, W2, b2, nullptr, hB, D_HID, D_HID);
    // L3: hB @ W3 + b3, relu -> hA
    sgemm_kernel<true,  false><<<dim3(gM, 2), 256>>>(hB, D_HID, W3, b3, nullptr, hA, D_HID, D_HID);
    // density head (reads hA)
    density_kernel<<<NPTS * 32 / 256, 256>>>(hA, Wsig, bsig);
    // feat: hA @ Wfeat + bfeat (no relu) -> hB
    sgemm_kernel<false, false><<<dim3(gM, 2), 256>>>(hA, D_HID, Wfeat, bfeat, nullptr, hB, D_HID, D_HID);
    // dir layer: relu(hB @ Wdir[0:256] + bdir + de_term[ray]) -> hd
    sgemm_kernel<true,  true ><<<dim3(gM, 1), 256>>>(hB, D_HID, Wdir, bdir, det, hd, DHD, D_HID);
    // rgb head
    rgb_kernel<<<NPTS * 32 / 256, 256>>>(Wrgb, brgb);
    // composite
    render_kernel<<<R_RAYS / 256, 256>>>(out);
}

// round 5
// speedup vs baseline: 1.0048x; 1.0048x over previous
#include <cuda_runtime.h>
#include <math.h>
#include <stdint.h>

// ---------------- problem constants ----------------
#define R_RAYS   4096
#define NSAMP    64
#define NPTS     (R_RAYS * NSAMP)   // 262144
#define D_HID    256
#define DHD      128
#define PE_P     63
#define PE_PAD   64
#define PE_D     27
#define NEAR_F   2.0f
#define FAR_F    6.0f

// ---------------- device scratch (static, allowed) ----------------
__device__ float g_pe[(size_t)NPTS * PE_PAD];    // 64 MiB
__device__ float g_hA[(size_t)NPTS * D_HID];     // 256 MiB
__device__ float g_hB[(size_t)NPTS * D_HID];     // 256 MiB
__device__ float g_hd[(size_t)NPTS * DHD];       // 128 MiB
__device__ float g_density[NPTS];
__device__ float g_rgb[NPTS * 3];
__device__ float g_vd[R_RAYS * 3];
__device__ float g_de[R_RAYS * PE_D];
__device__ float g_det[R_RAYS * DHD];
__device__ float g_W1p[PE_PAD * D_HID];

// ---------------- small prep kernels ----------------

// Pad W1 [63,256] -> [64,256] with zero last row.
__global__ void pad_w1_kernel(const float* __restrict__ W1) {
    int idx = blockIdx.x * blockDim.x + threadIdx.x;   // 0..16383
    g_W1p[idx] = (idx < PE_P * D_HID) ? W1[idx] : 0.0f;
}

// Per-ray: normalize viewdir, compute dir posenc (L=4 -> 27 vals).
__global__ void prep_rays_kernel(const float* __restrict__ viewdirs) {
    int r = blockIdx.x * blockDim.x + threadIdx.x;
    if (r >= R_RAYS) return;
    float vx = viewdirs[r * 3 + 0];
    float vy = viewdirs[r * 3 + 1];
    float vz = viewdirs[r * 3 + 2];
    float inv = 1.0f / sqrtf(vx * vx + vy * vy + vz * vz);
    vx *= inv; vy *= inv; vz *= inv;
    g_vd[r * 3 + 0] = vx; g_vd[r * 3 + 1] = vy; g_vd[r * 3 + 2] = vz;
    float* de = g_de + (size_t)r * PE_D;
    de[0] = vx; de[1] = vy; de[2] = vz;
    float v[3] = {vx, vy, vz};
    float f = 1.0f;
#pragma unroll
    for (int l = 0; l < 4; ++l) {
#pragma unroll
        for (int c = 0; c < 3; ++c) {
            float sn, cs;
            sincosf(v[c] * f, &sn, &cs);
            de[3 + l * 6 + c]     = sn;
            de[3 + l * 6 + 3 + c] = cs;
        }
        f *= 2.0f;
    }
}

// Per point: compute sample position + positional encoding (L=10 -> 63 vals, pad to 64).
// One block per ray, 64 threads = 64 samples.
__global__ void prep_pe_kernel(const float* __restrict__ xyz) {
    int ray = blockIdx.x;
    int s   = threadIdx.x;
    float ox = xyz[ray * 3 + 0], oy = xyz[ray * 3 + 1], oz = xyz[ray * 3 + 2];
    float dx = g_vd[ray * 3 + 0], dy = g_vd[ray * 3 + 1], dz = g_vd[ray * 3 + 2];
    float t  = (float)s * (1.0f / 63.0f);
    float sm = NEAR_F * (1.0f - t) + FAR_F * t;
    float p[3] = { fmaf(sm, dx, ox), fmaf(sm, dy, oy), fmaf(sm, dz, oz) };
    float* out = g_pe + (size_t)(ray * NSAMP + s) * PE_PAD;
    out[0] = p[0]; out[1] = p[1]; out[2] = p[2];
    float f = 1.0f;
#pragma unroll
    for (int l = 0; l < 10; ++l) {
#pragma unroll
        for (int c = 0; c < 3; ++c) {
            float sn, cs;
            sincosf(p[c] * f, &sn, &cs);
            out[3 + l * 6 + c]     = sn;
            out[3 + l * 6 + 3 + c] = cs;
        }
        f *= 2.0f;
    }
    out[63] = 0.0f;
}

// de_term[r, n] = sum_k de[r,k] * Wdir[256+k, n]   (the concat tail of the dir layer)
__global__ void de_term_kernel(const float* __restrict__ Wdir) {
    int t = blockIdx.x * blockDim.x + threadIdx.x;   // R_RAYS*DHD threads
    int r = t >> 7;
    int n = t & 127;
    const float* de = g_de + (size_t)r * PE_D;
    float s = 0.0f;
#pragma unroll
    for (int k = 0; k < PE_D; ++k)
        s = fmaf(de[k], Wdir[(size_t)(D_HID + k) * DHD + n], s);
    g_det[(size_t)r * DHD + n] = s;
}

// ---------------- tiled fp32 GEMM with packed f32x2 FMA ----------------
// C = act(A[M,lda] @ B[K,N] + bias + rowbias)
// BM=BN=128, BK=16, 256 threads, 8x8 per thread; accumulators held as f32x2
// pairs and updated with fma.rn.f32x2 (SASS FFMA2) -> 2 fp32 FLOP-pairs/inst.
template <bool RELU, bool ROWBIAS>
__global__ void __launch_bounds__(256)
sgemm_kernel(const float* __restrict__ A, int lda,
             const float* __restrict__ B,
             const float* __restrict__ bias,
             const float* __restrict__ rowbias,   // [R_RAYS, N], indexed by row>>6
             float* __restrict__ C, int N, int K)
{
    __shared__ float As[16][128];
    __shared__ float Bs[16][128];
    const int  tid = threadIdx.x;
    const long m0  = (long)blockIdx.x * 128;
    const int  n0  = blockIdx.y * 128;
    const int  aRow = tid >> 2;          // 0..63
    const int  aCol = (tid & 3) << 2;    // 0,4,8,12
    const int  bRow = tid >> 5;          // 0..7
    const int  bCol = (tid & 31) << 2;   // 0..124
    const int  ty = tid >> 4, tx = tid & 15;

    // acc2[i][j] packs C(i, 2j) in low lane, C(i, 2j+1) in high lane.
    unsigned long long acc2[8][4];
#pragma unroll
    for (int i = 0; i < 8; ++i)
#pragma unroll
        for (int j = 0; j < 4; ++j) acc2[i][j] = 0ull;

    for (int k0 = 0; k0 < K; k0 += 16) {
#pragma unroll
        for (int r = 0; r < 2; ++r) {
            int row = aRow + r * 64;
            float4 v = *reinterpret_cast<const float4*>(A + (m0 + row) * (long)lda + k0 + aCol);
            As[aCol + 0][row] = v.x;
            As[aCol + 1][row] = v.y;
            As[aCol + 2][row] = v.z;
            As[aCol + 3][row] = v.w;
        }
#pragma unroll
        for (int r = 0; r < 2; ++r) {
            int krow = bRow + r * 8;
            *reinterpret_cast<float4*>(&Bs[krow][bCol]) =
                *reinterpret_cast<const float4*>(B + (long)(k0 + krow) * N + n0 + bCol);
        }
        __syncthreads();
#pragma unroll
        for (int kk = 0; kk < 16; ++kk) {
            float ra[8];
            *(float4*)(ra)     = *(const float4*)&As[kk][ty * 8];
            *(float4*)(ra + 4) = *(const float4*)&As[kk][ty * 8 + 4];
            // B pairs: consecutive floats reinterpreted as packed f32x2 lanes
            // (low 32 bits = element 2j, high = 2j+1 — matches f32x2 layout).
            unsigned long long rb[4];
            {
                const ulonglong2* pb = reinterpret_cast<const ulonglong2*>(&Bs[kk][tx * 8]);
                ulonglong2 t0 = pb[0];
                ulonglong2 t1 = pb[1];
                rb[0] = t0.x; rb[1] = t0.y; rb[2] = t1.x; rb[3] = t1.y;
            }
            unsigned long long a2[8];
#pragma unroll
            for (int i = 0; i < 8; ++i)
                asm("mov.b64 %0, {%1, %1};" : "=l"(a2[i]) : "f"(ra[i]));
#pragma unroll
            for (int i = 0; i < 8; ++i)
#pragma unroll
                for (int j = 0; j < 4; ++j)
                    asm("fma.rn.f32x2 %0, %1, %2, %0;"
                        : "+l"(acc2[i][j]) : "l"(a2[i]), "l"(rb[j]));
        }
        __syncthreads();
    }

#pragma unroll
    for (int i = 0; i < 8; ++i) {
        long row = m0 + ty * 8 + i;
        const float* rbp = ROWBIAS ? (rowbias + (row >> 6) * (long)N) : nullptr;
        float c[8];
#pragma unroll
        for (int j = 0; j < 4; ++j)
            asm("mov.b64 {%0, %1}, %2;" : "=f"(c[2 * j]), "=f"(c[2 * j + 1]) : "l"(acc2[i][j]));
#pragma unroll
        for (int jv = 0; jv < 2; ++jv) {
            int col = n0 + tx * 8 + jv * 4;
            float o[4];
#pragma unroll
            for (int q = 0; q < 4; ++q) {
                float v = c[jv * 4 + q] + bias[col + q];
                if (ROWBIAS) v += rbp[col + q];
                if (RELU)    v = fmaxf(v, 0.0f);
                o[q] = v;
            }
            *reinterpret_cast<float4*>(C + row * (long)N + col) =
                make_float4(o[0], o[1], o[2], o[3]);
        }
    }
}

// ---------------- heads ----------------

__device__ __forceinline__ float warp_sum(float v) {
#pragma unroll
    for (int off = 16; off > 0; off >>= 1)
        v += __shfl_down_sync(0xffffffffu, v, off);
    return v;
}

// density[p] = h[p,:] . Wsig + bsig   (one warp per point)
__global__ void density_kernel(const float* __restrict__ h,
                               const float* __restrict__ Wsig,
                               const float* __restrict__ bsig) {
    int gw   = (blockIdx.x * blockDim.x + threadIdx.x) >> 5;
    int lane = threadIdx.x & 31;
    const float* hp = h + (size_t)gw * D_HID;
    float s = 0.0f;
#pragma unroll
    for (int i = 0; i < 8; ++i) {
        int k = lane + i * 32;
        s = fmaf(hp[k], Wsig[k], s);
    }
    s = warp_sum(s);
    if (lane == 0) g_density[gw] = s + bsig[0];
}

// rgb[p,:] = sigmoid(hd[p,:] @ Wrgb + brgb)   (one warp per point)
__global__ void rgb_kernel(const float* __restrict__ Wrgb,
                           const float* __restrict__ brgb) {
    int gw   = (blockIdx.x * blockDim.x + threadIdx.x) >> 5;
    int lane = threadIdx.x & 31;
    const float4 h = *reinterpret_cast<const float4*>(g_hd + (size_t)gw * DHD + lane * 4);
    int k = lane * 4;
    float a0, a1, a2;
    a0 = h.x * Wrgb[(k + 0) * 3 + 0] + h.y * Wrgb[(k + 1) * 3 + 0]
       + h.z * Wrgb[(k + 2) * 3 + 0] + h.w * Wrgb[(k + 3) * 3 + 0];
    a1 = h.x * Wrgb[(k + 0) * 3 + 1] + h.y * Wrgb[(k + 1) * 3 + 1]
       + h.z * Wrgb[(k + 2) * 3 + 1] + h.w * Wrgb[(k + 3) * 3 + 1];
    a2 = h.x * Wrgb[(k + 0) * 3 + 2] + h.y * Wrgb[(k + 1) * 3 + 2]
       + h.z * Wrgb[(k + 2) * 3 + 2] + h.w * Wrgb[(k + 3) * 3 + 2];
    a0 = warp_sum(a0); a1 = warp_sum(a1); a2 = warp_sum(a2);
    if (lane == 0) {
        g_rgb[gw * 3 + 0] = 1.0f / (1.0f + expf(-(a0 + brgb[0])));
        g_rgb[gw * 3 + 1] = 1.0f / (1.0f + expf(-(a1 + brgb[1])));
        g_rgb[gw * 3 + 2] = 1.0f / (1.0f + expf(-(a2 + brgb[2])));
    }
}

// ---------------- volume rendering (one thread per ray) ----------------
__global__ void render_kernel(float* __restrict__ out) {
    int ray = blockIdx.x * blockDim.x + threadIdx.x;
    if (ray >= R_RAYS) return;
    float T = 1.0f, r0 = 0.0f, r1 = 0.0f, r2 = 0.0f, depth = 0.0f, asum = 0.0f;
    for (int i = 0; i < NSAMP; ++i) {
        int p = ray * NSAMP + i;
        float ti = (float)i * (1.0f / 63.0f);
        float sm = NEAR_F * (1.0f - ti) + FAR_F * ti;
        float delta;
        if (i < NSAMP - 1) {
            float tn = (float)(i + 1) * (1.0f / 63.0f);
            delta = (NEAR_F * (1.0f - tn) + FAR_F * tn) - sm;
        } else {
            delta = 1e10f;
        }
        float sigma = fmaxf(g_density[p], 0.0f);
        float alpha = 1.0f - expf(-sigma * delta);
        float w = T * alpha;
        r0 += w * g_rgb[p * 3 + 0];
        r1 += w * g_rgb[p * 3 + 1];
        r2 += w * g_rgb[p * 3 + 2];
        depth += w * sm;
        asum  += w;
        T *= (1.0f - alpha);
    }
    float bk = 1.0f - asum;
    out[ray * 3 + 0] = r0 + bk;
    out[ray * 3 + 1] = r1 + bk;
    out[ray * 3 + 2] = r2 + bk;
    out[R_RAYS * 3 + ray] = depth;   // depth_map
    out[R_RAYS * 4 + ray] = asum;    // alpha_map
}

// ---------------- host launch ----------------
extern "C" void kernel_launch(void* const* d_in, const int* in_sizes, int n_in,
                              void* d_out, int out_size) {
    const float* xyz      = (const float*)d_in[0];
    const float* viewdirs = (const float*)d_in[1];
    const float* W1   = (const float*)d_in[2];
    const float* b1   = (const float*)d_in[3];
    const float* W2   = (const float*)d_in[4];
    const float* b2   = (const float*)d_in[5];
    const float* W3   = (const float*)d_in[6];
    const float* b3   = (const float*)d_in[7];
    const float* Wsig = (const float*)d_in[8];
    const float* bsig = (const float*)d_in[9];
    const float* Wfeat= (const float*)d_in[10];
    const float* bfeat= (const float*)d_in[11];
    const float* Wdir = (const float*)d_in[12];
    const float* bdir = (const float*)d_in[13];
    const float* Wrgb = (const float*)d_in[14];
    const float* brgb = (const float*)d_in[15];
    float* out = (float*)d_out;

    float *pe, *hA, *hB, *hd, *det, *w1p;
    cudaGetSymbolAddress((void**)&pe,  g_pe);
    cudaGetSymbolAddress((void**)&hA,  g_hA);
    cudaGetSymbolAddress((void**)&hB,  g_hB);
    cudaGetSymbolAddress((void**)&hd,  g_hd);
    cudaGetSymbolAddress((void**)&det, g_det);
    cudaGetSymbolAddress((void**)&w1p, g_W1p);

    // prep
    pad_w1_kernel<<<PE_PAD * D_HID / 256, 256>>>(W1);
    prep_rays_kernel<<<R_RAYS / 256, 256>>>(viewdirs);
    prep_pe_kernel<<<R_RAYS, NSAMP>>>(xyz);
    de_term_kernel<<<R_RAYS * DHD / 256, 256>>>(Wdir);

    const int gM = NPTS / 128;   // 2048
    // L1: pe[*,64] @ W1p[64,256] + b1, relu -> hA
    sgemm_kernel<true,  false><<<dim3(gM, 2), 256>>>(pe, PE_PAD, w1p, b1, nullptr, hA, D_HID, PE_PAD);
    // L2: hA @ W2 + b2, relu -> hB
    sgemm_kernel<true,  false><<<dim3(gM, 2), 256>>>(hA, D_HID, W2, b2, nullptr, hB, D_HID, D_HID);
    // L3: hB @ W3 + b3, relu -> hA
    sgemm_kernel<true,  false><<<dim3(gM, 2), 256>>>(hB, D_HID, W3, b3, nullptr, hA, D_HID, D_HID);
    // density head (reads hA)
    density_kernel<<<NPTS * 32 / 256, 256>>>(hA, Wsig, bsig);
    // feat: hA @ Wfeat + bfeat (no relu) -> hB
    sgemm_kernel<false, false><<<dim3(gM, 2), 256>>>(hA, D_HID, Wfeat, bfeat, nullptr, hB, D_HID, D_HID);
    // dir layer: relu(hB @ Wdir[0:256] + bdir + de_term[ray]) -> hd
    sgemm_kernel<true,  true ><<<dim3(gM, 1), 256>>>(hB, D_HID, Wdir, bdir, det, hd, DHD, D_HID);
    // rgb head
    rgb_kernel<<<NPTS * 32 / 256, 256>>>(Wrgb, brgb);
    // composite
    render_kernel<<<R_RAYS / 256, 256>>>(out);
}

// round 7
// speedup vs baseline: 1.7469x; 1.7386x over previous
#include <cuda_runtime.h>
#include <cuda_bf16.h>
#include <math.h>
#include <stdint.h>

// ---------------- problem constants ----------------
#define R_RAYS   4096
#define NSAMP    64
#define NPTS     (R_RAYS * NSAMP)   // 262144
#define D_HID    256
#define DHD      128
#define PE_P     63
#define PE_PAD   64
#define PE_D     27
#define NEAR_F   2.0f
#define FAR_F    6.0f

// ---- arch-specific feature gate (tcgen05 only legal in sm_103a/..a passes) ----
#if defined(__CUDA_ARCH__) && \
    (defined(__CUDA_ARCH_FEAT_SM103_ALL) || defined(__CUDA_ARCH_FEAT_SM100_ALL) || \
     defined(__CUDA_ARCH_SPECIFIC__) || defined(__CUDA_ARCH_FAMILY_SPECIFIC__))
#define HAS_TCGEN05 1
#else
#define HAS_TCGEN05 0
#endif

// ---------------- device scratch (static, allowed) ----------------
// Activations stored as packed bf16 (hi in low 16, lo in high 16) = 4B/elt.
__device__ uint32_t g_pe32[(size_t)NPTS * PE_PAD];   // 64 MiB
__device__ uint32_t g_A32[(size_t)NPTS * D_HID];     // 256 MiB
__device__ uint32_t g_B32[(size_t)NPTS * D_HID];     // 256 MiB
__device__ uint32_t g_hd32[(size_t)NPTS * DHD];      // 128 MiB
__device__ float    g_density[NPTS];
__device__ float    g_rgb[NPTS * 3];
__device__ float    g_vd[R_RAYS * 3];
__device__ float    g_de[R_RAYS * PE_D];
__device__ float    g_det[R_RAYS * DHD];
// Transposed + split weights: [N rows, Kpad cols] packed uint32.
__device__ uint32_t g_w1t[D_HID * PE_PAD];
__device__ uint32_t g_w2t[D_HID * D_HID];
__device__ uint32_t g_w3t[D_HID * D_HID];
__device__ uint32_t g_wft[D_HID * D_HID];
__device__ uint32_t g_wdt[DHD * D_HID];

// ---------------- bf16 split helpers ----------------
__device__ __forceinline__ uint32_t pack_split(float v) {
    __nv_bfloat16 h = __float2bfloat16_rn(v);
    float hf = __bfloat162float(h);
    __nv_bfloat16 l = __float2bfloat16_rn(v - hf);
    return (uint32_t)__bfloat16_as_ushort(h) | ((uint32_t)__bfloat16_as_ushort(l) << 16);
}
__device__ __forceinline__ float unpack_sum(uint32_t p) {
    __nv_bfloat16 h = __ushort_as_bfloat16((unsigned short)(p & 0xffffu));
    __nv_bfloat16 l = __ushort_as_bfloat16((unsigned short)(p >> 16));
    return __bfloat162float(h) + __bfloat162float(l);
}

#define SMEM_SWIZZLE_128B(off) ((off) ^ (((off) >> 3) & 0x70))

#if HAS_TCGEN05
// ---------------- PTX helpers (from verified sm_103a examples) ----------------
__device__ __forceinline__ uint32_t smem_to_u32(const void* p) {
    uint32_t a;
    asm("{ .reg .u64 t; cvta.to.shared.u64 t, %1; cvt.u32.u64 %0, t; }" : "=r"(a) : "l"(p));
    return a;
}
__device__ __forceinline__ uint32_t elect_one_pred() {
    uint32_t pred;
    asm volatile("{\n\t.reg .pred p;\n\telect.sync _|p, 0xFFFFFFFF;\n\tselp.b32 %0, 1, 0, p;\n\t}"
                 : "=r"(pred));
    return pred;
}
static constexpr uint64_t SMEM_DESC_BASE_SW128 =
    (uint64_t(2) << 61) | (uint64_t(1) << 46) | (uint64_t(64) << 32) | (uint64_t(1) << 16);
#define MAKE_SMEM_DESC(addr) (SMEM_DESC_BASE_SW128 | ((uint64_t)((addr) >> 4) & 0x3FFF))

#define MBARRIER_INIT(mbar, cnt) \
    asm volatile("mbarrier.init.shared.b64 [%0], %1;" :: "r"((uint32_t)(mbar)), "r"((uint32_t)(cnt)) : "memory")
#define MBARRIER_INVAL(mbar) \
    asm volatile("mbarrier.inval.shared.b64 [%0];" :: "r"((uint32_t)(mbar)) : "memory")
#define MBARRIER_WAIT_PARITY(mbar, par) do {                                        \
    uint32_t _m = (uint32_t)(mbar); uint32_t _p = (uint32_t)(par); uint32_t _d;     \
    asm volatile("{\n\t.reg .pred p;\n\t"                                           \
        "mbarrier.try_wait.parity.acquire.cta.shared::cta.b64 p, [%1], %2;\n\t"     \
        "selp.b32 %0, 1, 0, p;\n\t}" : "=r"(_d) : "r"(_m), "r"(_p) : "memory");     \
    if (!_d) {                                                                      \
        asm volatile("{\n\t.reg .pred P1;\n\t"                                      \
            "WAIT_LOOP_%=:\n\t"                                                     \
            "mbarrier.try_wait.parity.acquire.cta.shared::cta.b64 P1, [%0], %1, 0x989680;\n\t" \
            "@P1 bra.uni WAIT_DONE_%=;\n\t"                                         \
            "bra.uni WAIT_LOOP_%=;\n\t"                                             \
            "WAIT_DONE_%=:\n\t}" :: "r"(_m), "r"(_p) : "memory");                   \
    }                                                                               \
} while (0)

#define TCGEN05_ALLOC(res, n) \
    asm volatile("tcgen05.alloc.cta_group::1.sync.aligned.shared::cta.b32 [%0], %1;" \
                 :: "r"((uint32_t)(res)), "r"((uint32_t)(n)) : "memory")
#define TCGEN05_DEALLOC(addr, n) \
    asm volatile("tcgen05.dealloc.cta_group::1.sync.aligned.b32 %0, %1;" :: "r"(addr), "r"((uint32_t)(n)))
#define TCGEN05_COMMIT(mbar) \
    asm volatile("tcgen05.commit.cta_group::1.mbarrier::arrive::one.shared::cluster.b64 [%0];" \
                 :: "r"((uint32_t)(mbar)) : "memory")
#define TCGEN05_WAIT_LD()  asm volatile("tcgen05.wait::ld.sync.aligned;" ::: "memory")
#define TCGEN05_FENCE_AFTER()  asm volatile("tcgen05.fence::after_thread_sync;" ::: "memory")
#define TCGEN05_FENCE_BEFORE() asm volatile("tcgen05.fence::before_thread_sync;" ::: "memory")

#define TCGEN05_LD_32X32B_X32(r, addr) \
    asm volatile("tcgen05.ld.sync.aligned.32x32b.x32.b32 " \
        "{%0, %1, %2, %3, %4, %5, %6, %7, %8, %9, %10, %11, %12, %13, %14, %15, " \
        " %16, %17, %18, %19, %20, %21, %22, %23, %24, %25, %26, %27, %28, %29, %30, %31}, [%32];" \
        : "=r"((r)[0]),  "=r"((r)[1]),  "=r"((r)[2]),  "=r"((r)[3]), \
          "=r"((r)[4]),  "=r"((r)[5]),  "=r"((r)[6]),  "=r"((r)[7]), \
          "=r"((r)[8]),  "=r"((r)[9]),  "=r"((r)[10]), "=r"((r)[11]), \
          "=r"((r)[12]), "=r"((r)[13]), "=r"((r)[14]), "=r"((r)[15]), \
          "=r"((r)[16]), "=r"((r)[17]), "=r"((r)[18]), "=r"((r)[19]), \
          "=r"((r)[20]), "=r"((r)[21]), "=r"((r)[22]), "=r"((r)[23]), \
          "=r"((r)[24]), "=r"((r)[25]), "=r"((r)[26]), "=r"((r)[27]), \
          "=r"((r)[28]), "=r"((r)[29]), "=r"((r)[30]), "=r"((r)[31]) \
        : "r"(addr))

// SS-mode cg1 bf16 MMA (A desc + B desc both in SMEM).
__device__ __forceinline__ void mma_bf16_ss(uint32_t d, uint64_t a, uint64_t b,
                                            uint32_t idesc, bool acc) {
    uint32_t en = acc ? 1u : 0u;
    asm volatile(
        "{\n\t.reg .pred p;\n\tsetp.ne.u32 p, %5, 0;\n\t"
        "tcgen05.mma.cta_group::1.kind::f16 [%0], %1, %2, %3, {%4, %4, %4, %4}, p;\n\t}"
        :: "r"(d), "l"(a), "l"(b), "r"(idesc), "r"(0u), "r"(en) : "memory");
}

// idesc: dtype=F32(1<<4), atype=BF16(1<<7), btype=BF16(1<<10), N=128(16<<17), M=128(8<<24)
static constexpr uint32_t IDESC_N128 = 0x8200490u;
#endif  // HAS_TCGEN05

// ---------------- small prep kernels ----------------
__global__ void conv_weight_kernel(const float* __restrict__ W, uint32_t* __restrict__ out,
                                   int K_in, int Kpad, int N) {
    int idx = blockIdx.x * blockDim.x + threadIdx.x;
    if (idx >= N * Kpad) return;
    int n = idx / Kpad, k = idx - n * Kpad;
    float v = (k < K_in) ? W[(size_t)k * N + n] : 0.0f;
    out[idx] = pack_split(v);
}

__global__ void prep_rays_kernel(const float* __restrict__ viewdirs) {
    int r = blockIdx.x * blockDim.x + threadIdx.x;
    if (r >= R_RAYS) return;
    float vx = viewdirs[r * 3 + 0], vy = viewdirs[r * 3 + 1], vz = viewdirs[r * 3 + 2];
    float inv = 1.0f / sqrtf(vx * vx + vy * vy + vz * vz);
    vx *= inv; vy *= inv; vz *= inv;
    g_vd[r * 3 + 0] = vx; g_vd[r * 3 + 1] = vy; g_vd[r * 3 + 2] = vz;
    float* de = g_de + (size_t)r * PE_D;
    de[0] = vx; de[1] = vy; de[2] = vz;
    float v[3] = {vx, vy, vz};
    float f = 1.0f;
#pragma unroll
    for (int l = 0; l < 4; ++l) {
#pragma unroll
        for (int c = 0; c < 3; ++c) {
            float sn, cs;
            sincosf(v[c] * f, &sn, &cs);
            de[3 + l * 6 + c] = sn;
            de[3 + l * 6 + 3 + c] = cs;
        }
        f *= 2.0f;
    }
}

__global__ void prep_pe_kernel(const float* __restrict__ xyz) {
    int ray = blockIdx.x;
    int s = threadIdx.x;
    float ox = xyz[ray * 3 + 0], oy = xyz[ray * 3 + 1], oz = xyz[ray * 3 + 2];
    float dx = g_vd[ray * 3 + 0], dy = g_vd[ray * 3 + 1], dz = g_vd[ray * 3 + 2];
    float t = (float)s * (1.0f / 63.0f);
    float sm = NEAR_F * (1.0f - t) + FAR_F * t;
    float p[3] = { fmaf(sm, dx, ox), fmaf(sm, dy, oy), fmaf(sm, dz, oz) };
    uint32_t* out = g_pe32 + (size_t)(ray * NSAMP + s) * PE_PAD;
    out[0] = pack_split(p[0]); out[1] = pack_split(p[1]); out[2] = pack_split(p[2]);
    float f = 1.0f;
#pragma unroll
    for (int l = 0; l < 10; ++l) {
#pragma unroll
        for (int c = 0; c < 3; ++c) {
            float sn, cs;
            sincosf(p[c] * f, &sn, &cs);
            out[3 + l * 6 + c]     = pack_split(sn);
            out[3 + l * 6 + 3 + c] = pack_split(cs);
        }
        f *= 2.0f;
    }
    out[63] = 0u;
}

__global__ void de_term_kernel(const float* __restrict__ Wdir) {
    int t = blockIdx.x * blockDim.x + threadIdx.x;
    int r = t >> 7;
    int n = t & 127;
    const float* de = g_de + (size_t)r * PE_D;
    float s = 0.0f;
#pragma unroll
    for (int k = 0; k < PE_D; ++k)
        s = fmaf(de[k], Wdir[(size_t)(D_HID + k) * DHD + n], s);
    g_det[(size_t)r * DHD + n] = s;
}

// ---------------- split-bf16 GEMM ----------------
// D[M=128/CTA, NT*128] = act( A(hi+lo) @ Wt(hi+lo)^T + bias (+rowbias) )
// A: [Mtot, K] packed.  Wt: [NT*128, K] packed (row n = weight column n).
// tcgen05 path: K chunked at 64; per chunk 3 passes (AhBh, AlBh, AhBl).
// fallback path (non-'a' PTX pass): scalar fp32 smem-tiled GEMM, same I/O.
template <int K, int NT, bool RELU, bool ROWBIAS>
__global__ void __launch_bounds__(256)
mma_gemm_kernel(const uint32_t* __restrict__ Apk,
                const uint32_t* __restrict__ Bpk,
                const float* __restrict__ bias,
                const float* __restrict__ rowbias,   // [R_RAYS, NT*128] or null
                uint32_t* __restrict__ Cpk)
{
    constexpr int NTOT = NT * 128;
#if HAS_TCGEN05
    constexpr int SM_TM = 0, SM_MBAR = 8;
    constexpr int SM_AH = 1024;
    constexpr int SM_AL = SM_AH + 16384;
    constexpr int SM_B  = SM_AL + 16384;     // per nh: hi @ +nh*32768, lo @ +nh*32768+16384
    extern __shared__ char smem[];
    const uint32_t smem_base = smem_to_u32(smem);
    const int tid = threadIdx.x;
    const int wid = tid >> 5;
    const int lane = tid & 31;
    const long m0 = (long)blockIdx.x * 128;

    if (wid == 0) TCGEN05_ALLOC(smem_base + SM_TM, 256);
    __syncthreads();
    uint32_t tmem_base;
    asm volatile("ld.shared.b32 %0, [%1];" : "=r"(tmem_base) : "r"(smem_base + SM_TM));
    if (tid == 0) MBARRIER_INIT(smem_base + SM_MBAR, 1);
    __syncthreads();

    uint32_t phase = 0;
    bool first = true;
    constexpr int NCH = K / 64;

    for (int kc = 0; kc < NCH; ++kc) {
        // ---- load A chunk [128 x 64] packed -> hi/lo bf16 tiles (SW128) ----
#pragma unroll
        for (int i = 0; i < 4; ++i) {
            int u = tid + i * 256;          // 0..1023
            int row = u >> 3;
            int k8 = (u & 7) * 8;
            const uint4* src = reinterpret_cast<const uint4*>(Apk + (m0 + row) * K + kc * 64 + k8);
            uint4 p0 = src[0], p1 = src[1];
            uint32_t h0 = (p0.x & 0xffffu) | (p0.y << 16);
            uint32_t h1 = (p0.z & 0xffffu) | (p0.w << 16);
            uint32_t h2 = (p1.x & 0xffffu) | (p1.y << 16);
            uint32_t h3 = (p1.z & 0xffffu) | (p1.w << 16);
            uint32_t l0 = (p0.x >> 16) | (p0.y & 0xffff0000u);
            uint32_t l1 = (p0.z >> 16) | (p0.w & 0xffff0000u);
            uint32_t l2 = (p1.x >> 16) | (p1.y & 0xffff0000u);
            uint32_t l3 = (p1.z >> 16) | (p1.w & 0xffff0000u);
            uint32_t off = SMEM_SWIZZLE_128B((uint32_t)(row * 128 + k8 * 2));
            asm volatile("st.shared.v4.b32 [%0], {%1,%2,%3,%4};"
                         :: "r"(smem_base + SM_AH + off), "r"(h0), "r"(h1), "r"(h2), "r"(h3) : "memory");
            asm volatile("st.shared.v4.b32 [%0], {%1,%2,%3,%4};"
                         :: "r"(smem_base + SM_AL + off), "r"(l0), "r"(l1), "r"(l2), "r"(l3) : "memory");
        }
        // ---- load B chunk(s) [NT*128 x 64] packed -> hi/lo tiles ----
#pragma unroll
        for (int i = 0; i < 4 * NT; ++i) {
            int u = tid + i * 256;          // 0..NT*1024-1
            int nh = u >> 10;
            int rem = u & 1023;
            int row = rem >> 3;
            int k8 = (rem & 7) * 8;
            const uint4* src = reinterpret_cast<const uint4*>(Bpk + (size_t)(nh * 128 + row) * K + kc * 64 + k8);
            uint4 p0 = src[0], p1 = src[1];
            uint32_t h0 = (p0.x & 0xffffu) | (p0.y << 16);
            uint32_t h1 = (p0.z & 0xffffu) | (p0.w << 16);
            uint32_t h2 = (p1.x & 0xffffu) | (p1.y << 16);
            uint32_t h3 = (p1.z & 0xffffu) | (p1.w << 16);
            uint32_t l0 = (p0.x >> 16) | (p0.y & 0xffff0000u);
            uint32_t l1 = (p0.z >> 16) | (p0.w & 0xffff0000u);
            uint32_t l2 = (p1.x >> 16) | (p1.y & 0xffff0000u);
            uint32_t l3 = (p1.z >> 16) | (p1.w & 0xffff0000u);
            uint32_t off = SMEM_SWIZZLE_128B((uint32_t)(row * 128 + k8 * 2));
            uint32_t base = smem_base + SM_B + nh * 32768;
            asm volatile("st.shared.v4.b32 [%0], {%1,%2,%3,%4};"
                         :: "r"(base + off), "r"(h0), "r"(h1), "r"(h2), "r"(h3) : "memory");
            asm volatile("st.shared.v4.b32 [%0], {%1,%2,%3,%4};"
                         :: "r"(base + 16384 + off), "r"(l0), "r"(l1), "r"(l2), "r"(l3) : "memory");
        }
        __syncthreads();

        // ---- issue MMAs (warp 0, one thread) ----
        if (wid == 0) {
            if (elect_one_pred()) {
                uint64_t ah = MAKE_SMEM_DESC(smem_base + SM_AH);
                uint64_t al = MAKE_SMEM_DESC(smem_base + SM_AL);
#pragma unroll
                for (int nh = 0; nh < NT; ++nh) {
                    uint64_t bh = MAKE_SMEM_DESC(smem_base + SM_B + nh * 32768);
                    uint64_t bl = MAKE_SMEM_DESC(smem_base + SM_B + nh * 32768 + 16384);
                    uint32_t d = tmem_base + nh * 128;
#pragma unroll
                    for (int ks = 0; ks < 4; ++ks)
                        mma_bf16_ss(d, ah + ks * 2, bh + ks * 2, IDESC_N128, !(first && ks == 0));
#pragma unroll
                    for (int ks = 0; ks < 4; ++ks)
                        mma_bf16_ss(d, al + ks * 2, bh + ks * 2, IDESC_N128, true);
#pragma unroll
                    for (int ks = 0; ks < 4; ++ks)
                        mma_bf16_ss(d, ah + ks * 2, bl + ks * 2, IDESC_N128, true);
                }
                TCGEN05_COMMIT(smem_base + SM_MBAR);
            }
        }
        first = false;
        // all threads wait for MMA completion before next chunk overwrites SMEM
        MBARRIER_WAIT_PARITY(smem_base + SM_MBAR, phase);
        phase ^= 1;
    }

    TCGEN05_FENCE_AFTER();

    // ---- epilogue: WG0 -> cols 0..127, WG1 -> cols 128..255 ----
    const int wg = wid >> 2;            // column half
    const int sub = wid & 3;            // TMEM subpartition (rows sub*32..+31)
    if (NT == 2 || wg == 0) {
        const long grow = m0 + sub * 32 + lane;
        const float* rbp = ROWBIAS ? (rowbias + (grow >> 6) * (long)NTOT) : nullptr;
#pragma unroll
        for (int cb = 0; cb < 4; ++cb) {
            int col0 = wg * 128 + cb * 32;
            uint32_t regs[32];
            TCGEN05_LD_32X32B_X32(regs, tmem_base + col0);
            TCGEN05_WAIT_LD();
            uint32_t outp[32];
#pragma unroll
            for (int c = 0; c < 32; ++c) {
                float v = __uint_as_float(regs[c]) + bias[col0 + c];
                if (ROWBIAS) v += rbp[col0 + c];
                if (RELU) v = fmaxf(v, 0.0f);
                outp[c] = pack_split(v);
            }
            uint4* dst = reinterpret_cast<uint4*>(Cpk + grow * (long)NTOT + col0);
#pragma unroll
            for (int j = 0; j < 8; ++j)
                dst[j] = reinterpret_cast<uint4*>(outp)[j];
        }
    }
    TCGEN05_FENCE_BEFORE();
    __syncthreads();
    if (wid == 0) {
        if (elect_one_pred()) MBARRIER_INVAL(smem_base + SM_MBAR);
        TCGEN05_DEALLOC(tmem_base, 256);
    }
#else
    // ---------- scalar fp32 fallback (compiled only in non-'a' device passes) ----------
    extern __shared__ char smem[];
    float* As = reinterpret_cast<float*>(smem);            // [64][128] k-major
    float* Bs = As + 64 * 128;                             // [64][128] k-major
    const int tid = threadIdx.x;
    const long m0 = (long)blockIdx.x * 128;
    const int ty = tid >> 4, tx = tid & 15;

    for (int nh = 0; nh < NT; ++nh) {
        float acc[8][8];
#pragma unroll
        for (int i = 0; i < 8; ++i)
#pragma unroll
            for (int j = 0; j < 8; ++j) acc[i][j] = 0.0f;

        for (int kc = 0; kc < K / 64; ++kc) {
            __syncthreads();
#pragma unroll
            for (int i = 0; i < 32; ++i) {
                int u = tid + i * 256;       // 0..8191
                int row = u >> 6, k = u & 63;
                As[k * 128 + row] = unpack_sum(Apk[(m0 + row) * K + kc * 64 + k]);
            }
#pragma unroll
            for (int i = 0; i < 32; ++i) {
                int u = tid + i * 256;
                int col = u >> 6, k = u & 63;
                Bs[k * 128 + col] = unpack_sum(Bpk[(size_t)(nh * 128 + col) * K + kc * 64 + k]);
            }
            __syncthreads();
            for (int kk = 0; kk < 64; ++kk) {
                float ra[8], rb[8];
#pragma unroll
                for (int i = 0; i < 8; ++i) ra[i] = As[kk * 128 + ty * 8 + i];
#pragma unroll
                for (int j = 0; j < 8; ++j) rb[j] = Bs[kk * 128 + tx * 8 + j];
#pragma unroll
                for (int i = 0; i < 8; ++i)
#pragma unroll
                    for (int j = 0; j < 8; ++j)
                        acc[i][j] = fmaf(ra[i], rb[j], acc[i][j]);
            }
        }
        __syncthreads();
#pragma unroll
        for (int i = 0; i < 8; ++i) {
            long row = m0 + ty * 8 + i;
            const float* rbp = ROWBIAS ? (rowbias + (row >> 6) * (long)NTOT) : nullptr;
#pragma unroll
            for (int j = 0; j < 8; ++j) {
                int col = nh * 128 + tx * 8 + j;
                float v = acc[i][j] + bias[col];
                if (ROWBIAS) v += rbp[col];
                if (RELU) v = fmaxf(v, 0.0f);
                Cpk[row * (long)NTOT + col] = pack_split(v);
            }
        }
    }
#endif
}

// ---------------- heads ----------------
__device__ __forceinline__ float warp_sum(float v) {
#pragma unroll
    for (int off = 16; off > 0; off >>= 1)
        v += __shfl_down_sync(0xffffffffu, v, off);
    return v;
}

__global__ void density_kernel(const uint32_t* __restrict__ h,
                               const float* __restrict__ Wsig,
                               const float* __restrict__ bsig) {
    int gw = (blockIdx.x * blockDim.x + threadIdx.x) >> 5;
    int lane = threadIdx.x & 31;
    const uint32_t* hp = h + (size_t)gw * D_HID;
    float s = 0.0f;
#pragma unroll
    for (int i = 0; i < 8; ++i) {
        int k = lane + i * 32;
        s = fmaf(unpack_sum(hp[k]), Wsig[k], s);
    }
    s = warp_sum(s);
    if (lane == 0) g_density[gw] = s + bsig[0];
}

__global__ void rgb_kernel(const float* __restrict__ Wrgb,
                           const float* __restrict__ brgb) {
    int gw = (blockIdx.x * blockDim.x + threadIdx.x) >> 5;
    int lane = threadIdx.x & 31;
    const uint4 hp = *reinterpret_cast<const uint4*>(g_hd32 + (size_t)gw * DHD + lane * 4);
    float hv[4] = { unpack_sum(hp.x), unpack_sum(hp.y), unpack_sum(hp.z), unpack_sum(hp.w) };
    int k = lane * 4;
    float a0 = 0.0f, a1 = 0.0f, a2 = 0.0f;
#pragma unroll
    for (int q = 0; q < 4; ++q) {
        a0 = fmaf(hv[q], Wrgb[(k + q) * 3 + 0], a0);
        a1 = fmaf(hv[q], Wrgb[(k + q) * 3 + 1], a1);
        a2 = fmaf(hv[q], Wrgb[(k + q) * 3 + 2], a2);
    }
    a0 = warp_sum(a0); a1 = warp_sum(a1); a2 = warp_sum(a2);
    if (lane == 0) {
        g_rgb[gw * 3 + 0] = 1.0f / (1.0f + expf(-(a0 + brgb[0])));
        g_rgb[gw * 3 + 1] = 1.0f / (1.0f + expf(-(a1 + brgb[1])));
        g_rgb[gw * 3 + 2] = 1.0f / (1.0f + expf(-(a2 + brgb[2])));
    }
}

__global__ void render_kernel(float* __restrict__ out) {
    int ray = blockIdx.x * blockDim.x + threadIdx.x;
    if (ray >= R_RAYS) return;
    float T = 1.0f, r0 = 0.0f, r1 = 0.0f, r2 = 0.0f, depth = 0.0f, asum = 0.0f;
    for (int i = 0; i < NSAMP; ++i) {
        int p = ray * NSAMP + i;
        float ti = (float)i * (1.0f / 63.0f);
        float sm = NEAR_F * (1.0f - ti) + FAR_F * ti;
        float delta;
        if (i < NSAMP - 1) {
            float tn = (float)(i + 1) * (1.0f / 63.0f);
            delta = (NEAR_F * (1.0f - tn) + FAR_F * tn) - sm;
        } else {
            delta = 1e10f;
        }
        float sigma = fmaxf(g_density[p], 0.0f);
        float alpha = 1.0f - expf(-sigma * delta);
        float w = T * alpha;
        r0 += w * g_rgb[p * 3 + 0];
        r1 += w * g_rgb[p * 3 + 1];
        r2 += w * g_rgb[p * 3 + 2];
        depth += w * sm;
        asum += w;
        T *= (1.0f - alpha);
    }
    float bk = 1.0f - asum;
    out[ray * 3 + 0] = r0 + bk;
    out[ray * 3 + 1] = r1 + bk;
    out[ray * 3 + 2] = r2 + bk;
    out[R_RAYS * 3 + ray] = depth;
    out[R_RAYS * 4 + ray] = asum;
}

// ---------------- host launch ----------------
extern "C" void kernel_launch(void* const* d_in, const int* in_sizes, int n_in,
                              void* d_out, int out_size) {
    const float* xyz      = (const float*)d_in[0];
    const float* viewdirs = (const float*)d_in[1];
    const float* W1   = (const float*)d_in[2];
    const float* b1   = (const float*)d_in[3];
    const float* W2   = (const float*)d_in[4];
    const float* b2   = (const float*)d_in[5];
    const float* W3   = (const float*)d_in[6];
    const float* b3   = (const float*)d_in[7];
    const float* Wsig = (const float*)d_in[8];
    const float* bsig = (const float*)d_in[9];
    const float* Wfeat= (const float*)d_in[10];
    const float* bfeat= (const float*)d_in[11];
    const float* Wdir = (const float*)d_in[12];
    const float* bdir = (const float*)d_in[13];
    const float* Wrgb = (const float*)d_in[14];
    const float* brgb = (const float*)d_in[15];
    float* out = (float*)d_out;

    uint32_t *pe32, *A32, *B32, *hd32, *w1t, *w2t, *w3t, *wft, *wdt;
    float *det;
    cudaGetSymbolAddress((void**)&pe32, g_pe32);
    cudaGetSymbolAddress((void**)&A32,  g_A32);
    cudaGetSymbolAddress((void**)&B32,  g_B32);
    cudaGetSymbolAddress((void**)&hd32, g_hd32);
    cudaGetSymbolAddress((void**)&w1t,  g_w1t);
    cudaGetSymbolAddress((void**)&w2t,  g_w2t);
    cudaGetSymbolAddress((void**)&w3t,  g_w3t);
    cudaGetSymbolAddress((void**)&wft,  g_wft);
    cudaGetSymbolAddress((void**)&wdt,  g_wdt);
    cudaGetSymbolAddress((void**)&det,  g_det);

    // dynamic smem opt-in (host-side, not captured; idempotent)
    constexpr int SMEM2 = 1024 + 32768 + 2 * 32768;   // 99328 (NT=2)
    constexpr int SMEM1 = 1024 + 32768 + 1 * 32768;   // 66560 (NT=1)
    cudaFuncSetAttribute(mma_gemm_kernel<PE_PAD, 2, true,  false>, cudaFuncAttributeMaxDynamicSharedMemorySize, SMEM2);
    cudaFuncSetAttribute(mma_gemm_kernel<D_HID,  2, true,  false>, cudaFuncAttributeMaxDynamicSharedMemorySize, SMEM2);
    cudaFuncSetAttribute(mma_gemm_kernel<D_HID,  2, false, false>, cudaFuncAttributeMaxDynamicSharedMemorySize, SMEM2);
    cudaFuncSetAttribute(mma_gemm_kernel<D_HID,  1, true,  true >, cudaFuncAttributeMaxDynamicSharedMemorySize, SMEM1);

    // ---- prep ----
    conv_weight_kernel<<<(D_HID * PE_PAD + 255) / 256, 256>>>(W1,   w1t, PE_P,  PE_PAD, D_HID);
    conv_weight_kernel<<<(D_HID * D_HID  + 255) / 256, 256>>>(W2,   w2t, D_HID, D_HID,  D_HID);
    conv_weight_kernel<<<(D_HID * D_HID  + 255) / 256, 256>>>(W3,   w3t, D_HID, D_HID,  D_HID);
    conv_weight_kernel<<<(D_HID * D_HID  + 255) / 256, 256>>>(Wfeat,wft, D_HID, D_HID,  D_HID);
    conv_weight_kernel<<<(DHD   * D_HID  + 255) / 256, 256>>>(Wdir, wdt, D_HID, D_HID,  DHD);
    prep_rays_kernel<<<R_RAYS / 256, 256>>>(viewdirs);
    prep_pe_kernel<<<R_RAYS, NSAMP>>>(xyz);
    de_term_kernel<<<R_RAYS * DHD / 256, 256>>>(Wdir);

    const int gM = NPTS / 128;   // 2048
    // L1: pe @ W1 + b1, relu -> A32
    mma_gemm_kernel<PE_PAD, 2, true,  false><<<gM, 256, SMEM2>>>(pe32, w1t, b1, nullptr, A32);
    // L2: A32 @ W2 + b2, relu -> B32
    mma_gemm_kernel<D_HID,  2, true,  false><<<gM, 256, SMEM2>>>(A32, w2t, b2, nullptr, B32);
    // L3: B32 @ W3 + b3, relu -> A32
    mma_gemm_kernel<D_HID,  2, true,  false><<<gM, 256, SMEM2>>>(B32, w3t, b3, nullptr, A32);
    // density head (reads A32)
    density_kernel<<<NPTS * 32 / 256, 256>>>(A32, Wsig, bsig);
    // feat: A32 @ Wfeat + bfeat (no relu) -> B32
    mma_gemm_kernel<D_HID,  2, false, false><<<gM, 256, SMEM2>>>(A32, wft, bfeat, nullptr, B32);
    // dir: relu(B32 @ Wdir[0:256] + bdir + de_term[ray]) -> hd32
    mma_gemm_kernel<D_HID,  1, true,  true ><<<gM, 256, SMEM1>>>(B32, wdt, bdir, det, hd32);
    // rgb head
    rgb_kernel<<<NPTS * 32 / 256, 256>>>(Wrgb, brgb);
    // composite
    render_kernel<<<R_RAYS / 256, 256>>>(out);
}

// round 11
// speedup vs baseline: 2.1226x; 1.2151x over previous
#include <cuda_runtime.h>
#include <cuda_bf16.h>
#include <math.h>
#include <stdint.h>

// ---------------- problem constants ----------------
#define R_RAYS   4096
#define NSAMP    64
#define NPTS     (R_RAYS * NSAMP)   // 262144
#define D_HID    256
#define DHD      128
#define PE_P     63
#define PE_PAD   64
#define PE_D     27
#define NEAR_F   2.0f
#define FAR_F    6.0f

// ---- arch-specific feature gate (tcgen05 only legal in sm_103a/..a passes) ----
#if defined(__CUDA_ARCH__) && \
    (defined(__CUDA_ARCH_FEAT_SM103_ALL) || defined(__CUDA_ARCH_FEAT_SM100_ALL) || \
     defined(__CUDA_ARCH_SPECIFIC__) || defined(__CUDA_ARCH_FAMILY_SPECIFIC__))
#define HAS_TCGEN05 1
#else
#define HAS_TCGEN05 0
#endif

// ---------------- device scratch (static, allowed) ----------------
// Activations stored as packed bf16 (hi in low 16, lo in high 16) = 4B/elt.
__device__ uint32_t g_pe32[(size_t)NPTS * PE_PAD];   // 64 MiB
__device__ uint32_t g_A32[(size_t)NPTS * D_HID];     // 256 MiB
__device__ uint32_t g_B32[(size_t)NPTS * D_HID];     // 256 MiB
__device__ float    g_density[NPTS];
__device__ float    g_rgb[NPTS * 3];
__device__ float    g_vd[R_RAYS * 3];
__device__ float    g_de[R_RAYS * PE_D];
__device__ float    g_det[R_RAYS * DHD];
// Transposed + split weights: [N rows, Kpad cols] packed uint32.
__device__ uint32_t g_w1t[D_HID * PE_PAD];
__device__ uint32_t g_w2t[D_HID * D_HID];
__device__ uint32_t g_w3t[D_HID * D_HID];
__device__ uint32_t g_wft[D_HID * D_HID];
__device__ uint32_t g_wdt[DHD * D_HID];

// ---------------- bf16 split helpers ----------------
__device__ __forceinline__ uint32_t pack_split(float v) {
    __nv_bfloat16 h = __float2bfloat16_rn(v);
    float hf = __bfloat162float(h);
    __nv_bfloat16 l = __float2bfloat16_rn(v - hf);
    return (uint32_t)__bfloat16_as_ushort(h) | ((uint32_t)__bfloat16_as_ushort(l) << 16);
}
__device__ __forceinline__ float unpack_sum(uint32_t p) {
    __nv_bfloat16 h = __ushort_as_bfloat16((unsigned short)(p & 0xffffu));
    __nv_bfloat16 l = __ushort_as_bfloat16((unsigned short)(p >> 16));
    return __bfloat162float(h) + __bfloat162float(l);
}

#define SMEM_SWIZZLE_128B(off) ((off) ^ (((off) >> 3) & 0x70))

#if HAS_TCGEN05
// ---------------- PTX helpers (from verified sm_103a examples) ----------------
__device__ __forceinline__ uint32_t smem_to_u32(const void* p) {
    uint32_t a;
    asm("{ .reg .u64 t; cvta.to.shared.u64 t, %1; cvt.u32.u64 %0, t; }" : "=r"(a) : "l"(p));
    return a;
}
__device__ __forceinline__ uint32_t elect_one_pred() {
    uint32_t pred;
    asm volatile("{\n\t.reg .pred p;\n\telect.sync _|p, 0xFFFFFFFF;\n\tselp.b32 %0, 1, 0, p;\n\t}"
                 : "=r"(pred));
    return pred;
}
static constexpr uint64_t SMEM_DESC_BASE_SW128 =
    (uint64_t(2) << 61) | (uint64_t(1) << 46) | (uint64_t(64) << 32) | (uint64_t(1) << 16);
#define MAKE_SMEM_DESC(addr) (SMEM_DESC_BASE_SW128 | ((uint64_t)((addr) >> 4) & 0x3FFF))

// Generic-proxy stores -> async-proxy (tcgen05.mma) reads REQUIRE this fence.
#define FENCE_PROXY_ASYNC() \
    asm volatile("fence.proxy.async.shared::cta;" ::: "memory")

#define MBARRIER_INIT(mbar, cnt) \
    asm volatile("mbarrier.init.shared.b64 [%0], %1;" :: "r"((uint32_t)(mbar)), "r"((uint32_t)(cnt)) : "memory")
#define MBARRIER_INVAL(mbar) \
    asm volatile("mbarrier.inval.shared.b64 [%0];" :: "r"((uint32_t)(mbar)) : "memory")
#define MBARRIER_WAIT_PARITY(mbar, par) do {                                        \
    uint32_t _m = (uint32_t)(mbar); uint32_t _p = (uint32_t)(par); uint32_t _d;     \
    asm volatile("{\n\t.reg .pred p;\n\t"                                           \
        "mbarrier.try_wait.parity.acquire.cta.shared::cta.b64 p, [%1], %2;\n\t"     \
        "selp.b32 %0, 1, 0, p;\n\t}" : "=r"(_d) : "r"(_m), "r"(_p) : "memory");     \
    if (!_d) {                                                                      \
        asm volatile("{\n\t.reg .pred P1;\n\t"                                      \
            "WAIT_LOOP_%=:\n\t"                                                     \
            "mbarrier.try_wait.parity.acquire.cta.shared::cta.b64 P1, [%0], %1, 0x989680;\n\t" \
            "@P1 bra.uni WAIT_DONE_%=;\n\t"                                         \
            "bra.uni WAIT_LOOP_%=;\n\t"                                             \
            "WAIT_DONE_%=:\n\t}" :: "r"(_m), "r"(_p) : "memory");                   \
    }                                                                               \
} while (0)

#define TCGEN05_ALLOC(res, n) \
    asm volatile("tcgen05.alloc.cta_group::1.sync.aligned.shared::cta.b32 [%0], %1;" \
                 :: "r"((uint32_t)(res)), "r"((uint32_t)(n)) : "memory")
#define TCGEN05_DEALLOC(addr, n) \
    asm volatile("tcgen05.dealloc.cta_group::1.sync.aligned.b32 %0, %1;" :: "r"(addr), "r"((uint32_t)(n)))
#define TCGEN05_COMMIT(mbar) \
    asm volatile("tcgen05.commit.cta_group::1.mbarrier::arrive::one.shared::cluster.b64 [%0];" \
                 :: "r"((uint32_t)(mbar)) : "memory")
#define TCGEN05_WAIT_LD()  asm volatile("tcgen05.wait::ld.sync.aligned;" ::: "memory")
#define TCGEN05_FENCE_AFTER()  asm volatile("tcgen05.fence::after_thread_sync;" ::: "memory")
#define TCGEN05_FENCE_BEFORE() asm volatile("tcgen05.fence::before_thread_sync;" ::: "memory")

#define TCGEN05_LD_32X32B_X32(r, addr) \
    asm volatile("tcgen05.ld.sync.aligned.32x32b.x32.b32 " \
        "{%0, %1, %2, %3, %4, %5, %6, %7, %8, %9, %10, %11, %12, %13, %14, %15, " \
        " %16, %17, %18, %19, %20, %21, %22, %23, %24, %25, %26, %27, %28, %29, %30, %31}, [%32];" \
        : "=r"((r)[0]),  "=r"((r)[1]),  "=r"((r)[2]),  "=r"((r)[3]), \
          "=r"((r)[4]),  "=r"((r)[5]),  "=r"((r)[6]),  "=r"((r)[7]), \
          "=r"((r)[8]),  "=r"((r)[9]),  "=r"((r)[10]), "=r"((r)[11]), \
          "=r"((r)[12]), "=r"((r)[13]), "=r"((r)[14]), "=r"((r)[15]), \
          "=r"((r)[16]), "=r"((r)[17]), "=r"((r)[18]), "=r"((r)[19]), \
          "=r"((r)[20]), "=r"((r)[21]), "=r"((r)[22]), "=r"((r)[23]), \
          "=r"((r)[24]), "=r"((r)[25]), "=r"((r)[26]), "=r"((r)[27]), \
          "=r"((r)[28]), "=r"((r)[29]), "=r"((r)[30]), "=r"((r)[31]) \
        : "r"(addr))

// SS-mode cg1 bf16 MMA (A desc + B desc both in SMEM).
__device__ __forceinline__ void mma_bf16_ss(uint32_t d, uint64_t a, uint64_t b,
                                            uint32_t idesc, bool acc) {
    uint32_t en = acc ? 1u : 0u;
    asm volatile(
        "{\n\t.reg .pred p;\n\tsetp.ne.u32 p, %5, 0;\n\t"
        "tcgen05.mma.cta_group::1.kind::f16 [%0], %1, %2, %3, {%4, %4, %4, %4}, p;\n\t}"
        :: "r"(d), "l"(a), "l"(b), "r"(idesc), "r"(0u), "r"(en) : "memory");
}

// idesc: dtype=F32(1<<4), atype=BF16(1<<7), btype=BF16(1<<10), N=128(16<<17), M=128(8<<24)
static constexpr uint32_t IDESC_N128 = 0x8200490u;

// Load one logical [128 rows x 32 K] packed chunk into an SW128 tile with
// interleaved halves: hi bf16 at row bytes [0,64), lo at [64,128).
__device__ __forceinline__ void load_tile32(const uint32_t* __restrict__ src, int ldk,
                                            uint32_t dst, int tid) {
#pragma unroll
    for (int i = 0; i < 2; ++i) {
        int g = tid + i * 256;          // 0..511 groups of 8 packed
        int row = g >> 2;
        int kq = (g & 3) << 3;          // 0,8,16,24
        const uint4* s = reinterpret_cast<const uint4*>(src + (size_t)row * ldk + kq);
        uint4 p0 = s[0], p1 = s[1];
        uint32_t h0 = (p0.x & 0xffffu) | (p0.y << 16);
        uint32_t h1 = (p0.z & 0xffffu) | (p0.w << 16);
        uint32_t h2 = (p1.x & 0xffffu) | (p1.y << 16);
        uint32_t h3 = (p1.z & 0xffffu) | (p1.w << 16);
        uint32_t l0 = (p0.x >> 16) | (p0.y & 0xffff0000u);
        uint32_t l1 = (p0.z >> 16) | (p0.w & 0xffff0000u);
        uint32_t l2 = (p1.x >> 16) | (p1.y & 0xffff0000u);
        uint32_t l3 = (p1.z >> 16) | (p1.w & 0xffff0000u);
        uint32_t offh = SMEM_SWIZZLE_128B((uint32_t)(row * 128 + kq * 2));
        uint32_t offl = SMEM_SWIZZLE_128B((uint32_t)(row * 128 + 64 + kq * 2));
        asm volatile("st.shared.v4.b32 [%0], {%1,%2,%3,%4};"
                     :: "r"(dst + offh), "r"(h0), "r"(h1), "r"(h2), "r"(h3) : "memory");
        asm volatile("st.shared.v4.b32 [%0], {%1,%2,%3,%4};"
                     :: "r"(dst + offl), "r"(l0), "r"(l1), "r"(l2), "r"(l3) : "memory");
    }
}
#endif  // HAS_TCGEN05

// ---------------- small prep kernels ----------------
__global__ void conv_weight_kernel(const float* __restrict__ W, uint32_t* __restrict__ out,
                                   int K_in, int Kpad, int N) {
    int idx = blockIdx.x * blockDim.x + threadIdx.x;
    if (idx >= N * Kpad) return;
    int n = idx / Kpad, k = idx - n * Kpad;
    float v = (k < K_in) ? W[(size_t)k * N + n] : 0.0f;
    out[idx] = pack_split(v);
}

__global__ void prep_rays_kernel(const float* __restrict__ viewdirs) {
    int r = blockIdx.x * blockDim.x + threadIdx.x;
    if (r >= R_RAYS) return;
    float vx = viewdirs[r * 3 + 0], vy = viewdirs[r * 3 + 1], vz = viewdirs[r * 3 + 2];
    float inv = 1.0f / sqrtf(vx * vx + vy * vy + vz * vz);
    vx *= inv; vy *= inv; vz *= inv;
    g_vd[r * 3 + 0] = vx; g_vd[r * 3 + 1] = vy; g_vd[r * 3 + 2] = vz;
    float* de = g_de + (size_t)r * PE_D;
    de[0] = vx; de[1] = vy; de[2] = vz;
    float v[3] = {vx, vy, vz};
    float f = 1.0f;
#pragma unroll
    for (int l = 0; l < 4; ++l) {
#pragma unroll
        for (int c = 0; c < 3; ++c) {
            float sn, cs;
            sincosf(v[c] * f, &sn, &cs);
            de[3 + l * 6 + c] = sn;
            de[3 + l * 6 + 3 + c] = cs;
        }
        f *= 2.0f;
    }
}

__global__ void prep_pe_kernel(const float* __restrict__ xyz) {
    int ray = blockIdx.x;
    int s = threadIdx.x;
    float ox = xyz[ray * 3 + 0], oy = xyz[ray * 3 + 1], oz = xyz[ray * 3 + 2];
    float dx = g_vd[ray * 3 + 0], dy = g_vd[ray * 3 + 1], dz = g_vd[ray * 3 + 2];
    float t = (float)s * (1.0f / 63.0f);
    float sm = NEAR_F * (1.0f - t) + FAR_F * t;
    float p[3] = { fmaf(sm, dx, ox), fmaf(sm, dy, oy), fmaf(sm, dz, oz) };
    uint32_t* out = g_pe32 + (size_t)(ray * NSAMP + s) * PE_PAD;
    out[0] = pack_split(p[0]); out[1] = pack_split(p[1]); out[2] = pack_split(p[2]);
    float f = 1.0f;
#pragma unroll
    for (int l = 0; l < 10; ++l) {
#pragma unroll
        for (int c = 0; c < 3; ++c) {
            float sn, cs;
            sincosf(p[c] * f, &sn, &cs);
            out[3 + l * 6 + c]     = pack_split(sn);
            out[3 + l * 6 + 3 + c] = pack_split(cs);
        }
        f *= 2.0f;
    }
    out[63] = 0u;
}

__global__ void de_term_kernel(const float* __restrict__ Wdir) {
    int t = blockIdx.x * blockDim.x + threadIdx.x;
    int r = t >> 7;
    int n = t & 127;
    const float* de = g_de + (size_t)r * PE_D;
    float s = 0.0f;
#pragma unroll
    for (int k = 0; k < PE_D; ++k)
        s = fmaf(de[k], Wdir[(size_t)(D_HID + k) * DHD + n], s);
    g_det[(size_t)r * DHD + n] = s;
}

// ---------------- split-bf16 GEMM, 2-stage pipelined ----------------
// D[128, NT*128] = act( A(hi+lo) @ Wt(hi+lo)^T + bias (+rowbias) ), per CTA.
// HEAD: 0 none, 1 density (dot with hw -> hout[row]), 2 rgb (3 dots + sigmoid
// -> hout[row*3..], no C store).
template <int K, int NT, bool RELU, bool ROWBIAS, int HEAD>
__global__ void __launch_bounds__(256)
mma_gemm_kernel(const uint32_t* __restrict__ Apk,
                const uint32_t* __restrict__ Bpk,
                const float* __restrict__ bias,
                const float* __restrict__ rowbias,
                uint32_t* __restrict__ Cpk,
                const float* __restrict__ hw,
                const float* __restrict__ hb,
                float* __restrict__ hout)
{
    constexpr int NTOT = NT * 128;
    constexpr int NCH = K / 32;
#if HAS_TCGEN05
    constexpr int SM_TM = 0, SM_MB0 = 8, SM_MB1 = 16;
    constexpr int SM_DATA = 1024;
    constexpr int STAGE = (NT + 1) * 16384;       // A tile + NT B tiles, 16KB each
    extern __shared__ char smem[];
    const uint32_t smem_base = smem_to_u32(smem);
    const int tid = threadIdx.x;
    const int wid = tid >> 5;
    const int lane = tid & 31;
    const long m0 = (long)blockIdx.x * 128;

    if (wid == 0) TCGEN05_ALLOC(smem_base + SM_TM, 256);
    __syncthreads();
    uint32_t tmem_base;
    asm volatile("ld.shared.b32 %0, [%1];" : "=r"(tmem_base) : "r"(smem_base + SM_TM));
    if (tid == 0) {
        MBARRIER_INIT(smem_base + SM_MB0, 1);
        MBARRIER_INIT(smem_base + SM_MB1, 1);
    }
    __syncthreads();

    for (int kc = 0; kc < NCH; ++kc) {
        const int st = kc & 1;
        const uint32_t mb = smem_base + (st ? SM_MB1 : SM_MB0);
        if (kc >= 2) MBARRIER_WAIT_PARITY(mb, ((kc >> 1) - 1) & 1);

        const uint32_t tbase = smem_base + SM_DATA + st * STAGE;
        load_tile32(Apk + m0 * K + kc * 32, K, tbase, tid);
#pragma unroll
        for (int nh = 0; nh < NT; ++nh)
            load_tile32(Bpk + (size_t)nh * 128 * K + kc * 32, K,
                        tbase + 16384 + nh * 16384, tid);
        // Make generic-proxy stores visible to the async proxy BEFORE the
        // barrier that releases the MMA-issuing thread.
        FENCE_PROXY_ASYNC();
        __syncthreads();

        if (wid == 0) {
            if (elect_one_pred()) {
                uint64_t ad = MAKE_SMEM_DESC(tbase);
#pragma unroll
                for (int nh = 0; nh < NT; ++nh) {
                    uint64_t bd = MAKE_SMEM_DESC(tbase + 16384 + nh * 16384);
                    uint32_t d = tmem_base + nh * 128;
                    // pass 1: Ah*Bh  (hi at desc +0, lo at +4; ksteps +0,+2)
#pragma unroll
                    for (int ks = 0; ks < 2; ++ks)
                        mma_bf16_ss(d, ad + ks * 2, bd + ks * 2, IDESC_N128, !(kc == 0 && ks == 0));
                    // pass 2: Al*Bh
#pragma unroll
                    for (int ks = 0; ks < 2; ++ks)
                        mma_bf16_ss(d, ad + 4 + ks * 2, bd + ks * 2, IDESC_N128, true);
                    // pass 3: Ah*Bl
#pragma unroll
                    for (int ks = 0; ks < 2; ++ks)
                        mma_bf16_ss(d, ad + ks * 2, bd + 4 + ks * 2, IDESC_N128, true);
                }
                TCGEN05_COMMIT(mb);
            }
        }
    }

    // final waits: stage st received cnt commits; last commit parity = (cnt-1)&1
    {
        const int cnt0 = (NCH + 1) / 2, cnt1 = NCH / 2;
        MBARRIER_WAIT_PARITY(smem_base + SM_MB0, (cnt0 - 1) & 1);
        if (cnt1 > 0) MBARRIER_WAIT_PARITY(smem_base + SM_MB1, (cnt1 - 1) & 1);
    }
    TCGEN05_FENCE_AFTER();

    // ---- epilogue ----
    const int wg = wid >> 2;
    const int sub = wid & 3;
    float* sd = reinterpret_cast<float*>(smem + SM_DATA);   // stage area is free now
    if (NT == 2 || wg == 0) {
        const long grow = m0 + sub * 32 + lane;
        const float* rbp = ROWBIAS ? (rowbias + (grow >> 6) * (long)NTOT) : nullptr;
        float dpart = 0.0f;
        float a0 = 0.0f, a1 = 0.0f, a2 = 0.0f;
#pragma unroll
        for (int cb = 0; cb < 4; ++cb) {
            int col0 = wg * 128 + cb * 32;
            uint32_t regs[32];
            TCGEN05_LD_32X32B_X32(regs, tmem_base + col0);
            TCGEN05_WAIT_LD();
            uint32_t outp[32];
#pragma unroll
            for (int c = 0; c < 32; ++c) {
                float v = __uint_as_float(regs[c]) + bias[col0 + c];
                if (ROWBIAS) v += rbp[col0 + c];
                if (RELU) v = fmaxf(v, 0.0f);
                if (HEAD == 1) dpart = fmaf(v, hw[col0 + c], dpart);
                if (HEAD == 2) {
                    a0 = fmaf(v, hw[(col0 + c) * 3 + 0], a0);
                    a1 = fmaf(v, hw[(col0 + c) * 3 + 1], a1);
                    a2 = fmaf(v, hw[(col0 + c) * 3 + 2], a2);
                }
                outp[c] = pack_split(v);
            }
            if (HEAD != 2) {
                uint4* dst = reinterpret_cast<uint4*>(Cpk + grow * (long)NTOT + col0);
#pragma unroll
                for (int j = 0; j < 8; ++j)
                    dst[j] = reinterpret_cast<uint4*>(outp)[j];
            }
        }
        if (HEAD == 1) sd[wg * 128 + sub * 32 + lane] = dpart;
        if (HEAD == 2) {
            hout[grow * 3 + 0] = 1.0f / (1.0f + expf(-(a0 + hb[0])));
            hout[grow * 3 + 1] = 1.0f / (1.0f + expf(-(a1 + hb[1])));
            hout[grow * 3 + 2] = 1.0f / (1.0f + expf(-(a2 + hb[2])));
        }
    }
    if (HEAD == 1) {
        __syncthreads();
        if (tid < 128) hout[m0 + tid] = sd[tid] + sd[128 + tid] + hb[0];
    }
    TCGEN05_FENCE_BEFORE();
    __syncthreads();
    if (wid == 0) {
        if (elect_one_pred()) {
            MBARRIER_INVAL(smem_base + SM_MB0);
            MBARRIER_INVAL(smem_base + SM_MB1);
        }
        TCGEN05_DEALLOC(tmem_base, 256);
    }
#else
    // ---------- scalar fp32 fallback (non-'a' device passes only) ----------
    extern __shared__ char smem[];
    float* As = reinterpret_cast<float*>(smem);            // [32][128] k-major
    float* Bs = As + 32 * 128;                             // [32][128] k-major
    __shared__ float sd[128];
    __shared__ float sr[128 * 3];
    const int tid = threadIdx.x;
    const long m0 = (long)blockIdx.x * 128;
    const int ty = tid >> 4, tx = tid & 15;
    if (HEAD == 1 && tid < 128) sd[tid] = 0.0f;
    if (HEAD == 2) for (int i = tid; i < 384; i += 256) sr[i] = 0.0f;

    for (int nh = 0; nh < NT; ++nh) {
        float acc[8][8];
#pragma unroll
        for (int i = 0; i < 8; ++i)
#pragma unroll
            for (int j = 0; j < 8; ++j) acc[i][j] = 0.0f;

        for (int kc = 0; kc < NCH; ++kc) {
            __syncthreads();
#pragma unroll
            for (int i = 0; i < 16; ++i) {
                int u = tid + i * 256;       // 0..4095
                int row = u >> 5, k = u & 31;
                As[k * 128 + row] = unpack_sum(Apk[(m0 + row) * K + kc * 32 + k]);
            }
#pragma unroll
            for (int i = 0; i < 16; ++i) {
                int u = tid + i * 256;
                int col = u >> 5, k = u & 31;
                Bs[k * 128 + col] = unpack_sum(Bpk[(size_t)(nh * 128 + col) * K + kc * 32 + k]);
            }
            __syncthreads();
            for (int kk = 0; kk < 32; ++kk) {
                float ra[8], rb[8];
#pragma unroll
                for (int i = 0; i < 8; ++i) ra[i] = As[kk * 128 + ty * 8 + i];
#pragma unroll
                for (int j = 0; j < 8; ++j) rb[j] = Bs[kk * 128 + tx * 8 + j];
#pragma unroll
                for (int i = 0; i < 8; ++i)
#pragma unroll
                    for (int j = 0; j < 8; ++j)
                        acc[i][j] = fmaf(ra[i], rb[j], acc[i][j]);
            }
        }
        __syncthreads();
#pragma unroll
        for (int i = 0; i < 8; ++i) {
            long row = m0 + ty * 8 + i;
            const float* rbp = ROWBIAS ? (rowbias + (row >> 6) * (long)NTOT) : nullptr;
            float dpart = 0.0f, p0 = 0.0f, p1 = 0.0f, p2 = 0.0f;
#pragma unroll
            for (int j = 0; j < 8; ++j) {
                int col = nh * 128 + tx * 8 + j;
                float v = acc[i][j] + bias[col];
                if (ROWBIAS) v += rbp[col];
                if (RELU) v = fmaxf(v, 0.0f);
                if (HEAD == 1) dpart = fmaf(v, hw[col], dpart);
                if (HEAD == 2) {
                    p0 = fmaf(v, hw[col * 3 + 0], p0);
                    p1 = fmaf(v, hw[col * 3 + 1], p1);
                    p2 = fmaf(v, hw[col * 3 + 2], p2);
                }
                if (HEAD != 2) Cpk[row * (long)NTOT + col] = pack_split(v);
            }
            if (HEAD == 1) atomicAdd(&sd[ty * 8 + i], dpart);
            if (HEAD == 2) {
                atomicAdd(&sr[(ty * 8 + i) * 3 + 0], p0);
                atomicAdd(&sr[(ty * 8 + i) * 3 + 1], p1);
                atomicAdd(&sr[(ty * 8 + i) * 3 + 2], p2);
            }
        }
    }
    __syncthreads();
    if (HEAD == 1 && tid < 128) hout[m0 + tid] = sd[tid] + hb[0];
    if (HEAD == 2 && tid < 128) {
#pragma unroll
        for (int j = 0; j < 3; ++j)
            hout[(m0 + tid) * 3 + j] = 1.0f / (1.0f + expf(-(sr[tid * 3 + j] + hb[j])));
    }
#endif
}

// ---------------- volume rendering (one thread per ray) ----------------
__global__ void render_kernel(float* __restrict__ out) {
    int ray = blockIdx.x * blockDim.x + threadIdx.x;
    if (ray >= R_RAYS) return;
    float T = 1.0f, r0 = 0.0f, r1 = 0.0f, r2 = 0.0f, depth = 0.0f, asum = 0.0f;
    for (int i = 0; i < NSAMP; ++i) {
        int p = ray * NSAMP + i;
        float ti = (float)i * (1.0f / 63.0f);
        float sm = NEAR_F * (1.0f - ti) + FAR_F * ti;
        float delta;
        if (i < NSAMP - 1) {
            float tn = (float)(i + 1) * (1.0f / 63.0f);
            delta = (NEAR_F * (1.0f - tn) + FAR_F * tn) - sm;
        } else {
            delta = 1e10f;
        }
        float sigma = fmaxf(g_density[p], 0.0f);
        float alpha = 1.0f - expf(-sigma * delta);
        float w = T * alpha;
        r0 += w * g_rgb[p * 3 + 0];
        r1 += w * g_rgb[p * 3 + 1];
        r2 += w * g_rgb[p * 3 + 2];
        depth += w * sm;
        asum += w;
        T *= (1.0f - alpha);
    }
    float bk = 1.0f - asum;
    out[ray * 3 + 0] = r0 + bk;
    out[ray * 3 + 1] = r1 + bk;
    out[ray * 3 + 2] = r2 + bk;
    out[R_RAYS * 3 + ray] = depth;
    out[R_RAYS * 4 + ray] = asum;
}

// ---------------- host launch ----------------
extern "C" void kernel_launch(void* const* d_in, const int* in_sizes, int n_in,
                              void* d_out, int out_size) {
    const float* xyz      = (const float*)d_in[0];
    const float* viewdirs = (const float*)d_in[1];
    const float* W1   = (const float*)d_in[2];
    const float* b1   = (const float*)d_in[3];
    const float* W2   = (const float*)d_in[4];
    const float* b2   = (const float*)d_in[5];
    const float* W3   = (const float*)d_in[6];
    const float* b3   = (const float*)d_in[7];
    const float* Wsig = (const float*)d_in[8];
    const float* bsig = (const float*)d_in[9];
    const float* Wfeat= (const float*)d_in[10];
    const float* bfeat= (const float*)d_in[11];
    const float* Wdir = (const float*)d_in[12];
    const float* bdir = (const float*)d_in[13];
    const float* Wrgb = (const float*)d_in[14];
    const float* brgb = (const float*)d_in[15];
    float* out = (float*)d_out;

    uint32_t *pe32, *A32, *B32, *w1t, *w2t, *w3t, *wft, *wdt;
    float *det, *dens, *rgbp;
    cudaGetSymbolAddress((void**)&pe32, g_pe32);
    cudaGetSymbolAddress((void**)&A32,  g_A32);
    cudaGetSymbolAddress((void**)&B32,  g_B32);
    cudaGetSymbolAddress((void**)&w1t,  g_w1t);
    cudaGetSymbolAddress((void**)&w2t,  g_w2t);
    cudaGetSymbolAddress((void**)&w3t,  g_w3t);
    cudaGetSymbolAddress((void**)&wft,  g_wft);
    cudaGetSymbolAddress((void**)&wdt,  g_wdt);
    cudaGetSymbolAddress((void**)&det,  g_det);
    cudaGetSymbolAddress((void**)&dens, g_density);
    cudaGetSymbolAddress((void**)&rgbp, g_rgb);

    // dynamic smem opt-in (host-side, idempotent)
    constexpr int SMEM2 = 1024 + 2 * 3 * 16384;   // 99328 (NT=2, 2 stages)
    constexpr int SMEM1 = 1024 + 2 * 2 * 16384;   // 66560 (NT=1, 2 stages)
    cudaFuncSetAttribute(mma_gemm_kernel<PE_PAD, 2, true,  false, 0>, cudaFuncAttributeMaxDynamicSharedMemorySize, SMEM2);
    cudaFuncSetAttribute(mma_gemm_kernel<D_HID,  2, true,  false, 0>, cudaFuncAttributeMaxDynamicSharedMemorySize, SMEM2);
    cudaFuncSetAttribute(mma_gemm_kernel<D_HID,  2, true,  false, 1>, cudaFuncAttributeMaxDynamicSharedMemorySize, SMEM2);
    cudaFuncSetAttribute(mma_gemm_kernel<D_HID,  2, false, false, 0>, cudaFuncAttributeMaxDynamicSharedMemorySize, SMEM2);
    cudaFuncSetAttribute(mma_gemm_kernel<D_HID,  1, true,  true,  2>, cudaFuncAttributeMaxDynamicSharedMemorySize, SMEM1);

    // ---- prep ----
    conv_weight_kernel<<<(D_HID * PE_PAD + 255) / 256, 256>>>(W1,   w1t, PE_P,  PE_PAD, D_HID);
    conv_weight_kernel<<<(D_HID * D_HID  + 255) / 256, 256>>>(W2,   w2t, D_HID, D_HID,  D_HID);
    conv_weight_kernel<<<(D_HID * D_HID  + 255) / 256, 256>>>(W3,   w3t, D_HID, D_HID,  D_HID);
    conv_weight_kernel<<<(D_HID * D_HID  + 255) / 256, 256>>>(Wfeat,wft, D_HID, D_HID,  D_HID);
    conv_weight_kernel<<<(DHD   * D_HID  + 255) / 256, 256>>>(Wdir, wdt, D_HID, D_HID,  DHD);
    prep_rays_kernel<<<R_RAYS / 256, 256>>>(viewdirs);
    prep_pe_kernel<<<R_RAYS, NSAMP>>>(xyz);
    de_term_kernel<<<R_RAYS * DHD / 256, 256>>>(Wdir);

    const int gM = NPTS / 128;   // 2048
    // L1: pe @ W1 + b1, relu -> A32
    mma_gemm_kernel<PE_PAD, 2, true,  false, 0><<<gM, 256, SMEM2>>>(pe32, w1t, b1, nullptr, A32, nullptr, nullptr, nullptr);
    // L2: A32 @ W2 + b2, relu -> B32
    mma_gemm_kernel<D_HID,  2, true,  false, 0><<<gM, 256, SMEM2>>>(A32, w2t, b2, nullptr, B32, nullptr, nullptr, nullptr);
    // L3: B32 @ W3 + b3, relu -> A32  (+ fused density head)
    mma_gemm_kernel<D_HID,  2, true,  false, 1><<<gM, 256, SMEM2>>>(B32, w3t, b3, nullptr, A32, Wsig, bsig, dens);
    // feat: A32 @ Wfeat + bfeat (no relu) -> B32
    mma_gemm_kernel<D_HID,  2, false, false, 0><<<gM, 256, SMEM2>>>(A32, wft, bfeat, nullptr, B32, nullptr, nullptr, nullptr);
    // dir: relu(B32 @ Wdir[0:256] + bdir + de_term) -> fused rgb head (no C store)
    mma_gemm_kernel<D_HID,  1, true,  true,  2><<<gM, 256, SMEM1>>>(B32, wdt, bdir, det, A32, Wrgb, brgb, rgbp);
    // composite
    render_kernel<<<R_RAYS / 256, 256>>>(out);
}

// round 12
// speedup vs baseline: 2.4652x; 1.1614x over previous
#include <cuda_runtime.h>
#include <cuda_bf16.h>
#include <math.h>
#include <stdint.h>

// ---------------- problem constants ----------------
#define R_RAYS   4096
#define NSAMP    64
#define NPTS     (R_RAYS * NSAMP)   // 262144
#define D_HID    256
#define DHD      128
#define PE_P     63
#define PE_PAD   64
#define PE_D     27
#define NEAR_F   2.0f
#define FAR_F    6.0f

// ---- arch-specific feature gate (tcgen05 only legal in sm_103a/..a passes) ----
#if defined(__CUDA_ARCH__) && \
    (defined(__CUDA_ARCH_FEAT_SM103_ALL) || defined(__CUDA_ARCH_FEAT_SM100_ALL) || \
     defined(__CUDA_ARCH_SPECIFIC__) || defined(__CUDA_ARCH_FAMILY_SPECIFIC__))
#define HAS_TCGEN05 1
#else
#define HAS_TCGEN05 0
#endif

// ---------------- device scratch (static, allowed) ----------------
__device__ float g_vd[R_RAYS * 3];
__device__ float g_det[R_RAYS * DHD];
// Pre-tiled weights: each tile is a 16KB SW128 image (hi bf16 bytes [0,64),
// lo bf16 bytes [64,128) per 128B row), laid out [NCH][NT][1024 uint4].
__device__ uint4 g_w1tile[2 * 2 * 1024];
__device__ uint4 g_w2tile[8 * 2 * 1024];
__device__ uint4 g_w3tile[8 * 2 * 1024];
__device__ uint4 g_wftile[8 * 2 * 1024];
__device__ uint4 g_wdtile[8 * 1 * 1024];

#define SMEM_SWIZZLE_128B(off) ((off) ^ (((off) >> 3) & 0x70))

// smem layout (fused kernel)
#define SM_TM    0
#define SM_MB0   8
#define SM_MB1   16
#define SM_SD    32                    // 256 floats (density partial)
#define SM_RGB   1056                  // 384 floats
#define SM_DENS  2592                  // 128 floats
#define SM_A     4096                  // 8 x 16KB A tiles
#define SM_B     (4096 + 8 * 16384)    // 2 stages x 32KB
#define SMEM_TOTAL (SM_B + 2 * 32768)  // 200704

// ---------------- bf16 split helpers ----------------
__device__ __forceinline__ void split_bf16(float v, uint32_t& h, uint32_t& l) {
    __nv_bfloat16 hb = __float2bfloat16_rn(v);
    float hf = __bfloat162float(hb);
    __nv_bfloat16 lb = __float2bfloat16_rn(v - hf);
    h = (uint32_t)__bfloat16_as_ushort(hb);
    l = (uint32_t)__bfloat16_as_ushort(lb);
}

// ---------------- small prep kernels ----------------
__global__ void prep_rays_kernel(const float* __restrict__ viewdirs) {
    int r = blockIdx.x * blockDim.x + threadIdx.x;
    if (r >= R_RAYS) return;
    float vx = viewdirs[r * 3 + 0], vy = viewdirs[r * 3 + 1], vz = viewdirs[r * 3 + 2];
    float inv = 1.0f / sqrtf(vx * vx + vy * vy + vz * vz);
    g_vd[r * 3 + 0] = vx * inv; g_vd[r * 3 + 1] = vy * inv; g_vd[r * 3 + 2] = vz * inv;
}

// de_term[r, n] = sum_k de[r,k] * Wdir[256+k, n]   (concat tail of dir layer)
__global__ void de_term_kernel(const float* __restrict__ Wdir) {
    int t = blockIdx.x * blockDim.x + threadIdx.x;
    int r = t >> 7;
    int n = t & 127;
    float vx = g_vd[r * 3 + 0], vy = g_vd[r * 3 + 1], vz = g_vd[r * 3 + 2];
    float de[PE_D];
    de[0] = vx; de[1] = vy; de[2] = vz;
    float v[3] = {vx, vy, vz};
    float f = 1.0f;
#pragma unroll
    for (int l = 0; l < 4; ++l) {
#pragma unroll
        for (int c = 0; c < 3; ++c) {
            float sn, cs;
            sincosf(v[c] * f, &sn, &cs);
            de[3 + l * 6 + c] = sn;
            de[3 + l * 6 + 3 + c] = cs;
        }
        f *= 2.0f;
    }
    float s = 0.0f;
#pragma unroll
    for (int k = 0; k < PE_D; ++k)
        s = fmaf(de[k], Wdir[(size_t)(D_HID + k) * DHD + n], s);
    g_det[(size_t)r * DHD + n] = s;
}

// Build 16KB SW128 weight-tile images from W [K_in x N] (row-major, fp32).
// One thread per 8 consecutive k of one (kc, nh, row).
__global__ void tile_weight_kernel(const float* __restrict__ W, uint4* __restrict__ tiles,
                                   int K_in, int N, int NT, int NCH) {
    int idx = blockIdx.x * blockDim.x + threadIdx.x;
    int total = NCH * NT * 512;
    if (idx >= total) return;
    int g = idx & 3;
    int row = (idx >> 2) & 127;
    int rest = idx >> 9;
    int nh = rest % NT;
    int kc = rest / NT;
    int n = nh * 128 + row;
    uint32_t h[4], l[4];
#pragma unroll
    for (int j = 0; j < 4; ++j) {
        uint32_t h0, l0, h1, l1;
        int k0 = kc * 32 + g * 8 + 2 * j;
        float v0 = (k0 < K_in) ? W[(size_t)k0 * N + n] : 0.0f;
        float v1 = (k0 + 1 < K_in) ? W[(size_t)(k0 + 1) * N + n] : 0.0f;
        split_bf16(v0, h0, l0);
        split_bf16(v1, h1, l1);
        h[j] = h0 | (h1 << 16);
        l[j] = l0 | (l1 << 16);
    }
    uint4* tb = tiles + (size_t)(kc * NT + nh) * 1024;
    uint32_t offh = SMEM_SWIZZLE_128B((uint32_t)(row * 128 + g * 16));
    uint32_t offl = SMEM_SWIZZLE_128B((uint32_t)(row * 128 + 64 + g * 16));
    tb[offh >> 4] = make_uint4(h[0], h[1], h[2], h[3]);
    uint32_t lo[4];
#pragma unroll
    for (int j = 0; j < 4; ++j) lo[j] = l[j];
    tb[offl >> 4] = make_uint4(lo[0], lo[1], lo[2], lo[3]);
}

#if HAS_TCGEN05
// ---------------- PTX helpers (from verified sm_103a examples) ----------------
__device__ __forceinline__ uint32_t smem_to_u32(const void* p) {
    uint32_t a;
    asm("{ .reg .u64 t; cvta.to.shared.u64 t, %1; cvt.u32.u64 %0, t; }" : "=r"(a) : "l"(p));
    return a;
}
__device__ __forceinline__ uint32_t elect_one_pred() {
    uint32_t pred;
    asm volatile("{\n\t.reg .pred p;\n\telect.sync _|p, 0xFFFFFFFF;\n\tselp.b32 %0, 1, 0, p;\n\t}"
                 : "=r"(pred));
    return pred;
}
static constexpr uint64_t SMEM_DESC_BASE_SW128 =
    (uint64_t(2) << 61) | (uint64_t(1) << 46) | (uint64_t(64) << 32) | (uint64_t(1) << 16);
#define MAKE_SMEM_DESC(addr) (SMEM_DESC_BASE_SW128 | ((uint64_t)((addr) >> 4) & 0x3FFF))

#define FENCE_PROXY_ASYNC() \
    asm volatile("fence.proxy.async.shared::cta;" ::: "memory")

#define MBARRIER_INIT(mbar, cnt) \
    asm volatile("mbarrier.init.shared.b64 [%0], %1;" :: "r"((uint32_t)(mbar)), "r"((uint32_t)(cnt)) : "memory")
#define MBARRIER_INVAL(mbar) \
    asm volatile("mbarrier.inval.shared.b64 [%0];" :: "r"((uint32_t)(mbar)) : "memory")
#define MBARRIER_WAIT_PARITY(mbar, par) do {                                        \
    uint32_t _m = (uint32_t)(mbar); uint32_t _p = (uint32_t)(par); uint32_t _d;     \
    asm volatile("{\n\t.reg .pred p;\n\t"                                           \
        "mbarrier.try_wait.parity.acquire.cta.shared::cta.b64 p, [%1], %2;\n\t"     \
        "selp.b32 %0, 1, 0, p;\n\t}" : "=r"(_d) : "r"(_m), "r"(_p) : "memory");     \
    if (!_d) {                                                                      \
        asm volatile("{\n\t.reg .pred P1;\n\t"                                      \
            "WAIT_LOOP_%=:\n\t"                                                     \
            "mbarrier.try_wait.parity.acquire.cta.shared::cta.b64 P1, [%0], %1, 0x989680;\n\t" \
            "@P1 bra.uni WAIT_DONE_%=;\n\t"                                         \
            "bra.uni WAIT_LOOP_%=;\n\t"                                             \
            "WAIT_DONE_%=:\n\t}" :: "r"(_m), "r"(_p) : "memory");                   \
    }                                                                               \
} while (0)

#define TCGEN05_ALLOC(res, n) \
    asm volatile("tcgen05.alloc.cta_group::1.sync.aligned.shared::cta.b32 [%0], %1;" \
                 :: "r"((uint32_t)(res)), "r"((uint32_t)(n)) : "memory")
#define TCGEN05_DEALLOC(addr, n) \
    asm volatile("tcgen05.dealloc.cta_group::1.sync.aligned.b32 %0, %1;" :: "r"(addr), "r"((uint32_t)(n)))
#define TCGEN05_COMMIT(mbar) \
    asm volatile("tcgen05.commit.cta_group::1.mbarrier::arrive::one.shared::cluster.b64 [%0];" \
                 :: "r"((uint32_t)(mbar)) : "memory")
#define TCGEN05_WAIT_LD()  asm volatile("tcgen05.wait::ld.sync.aligned;" ::: "memory")
#define TCGEN05_FENCE_AFTER()  asm volatile("tcgen05.fence::after_thread_sync;" ::: "memory")
#define TCGEN05_FENCE_BEFORE() asm volatile("tcgen05.fence::before_thread_sync;" ::: "memory")

#define TCGEN05_LD_32X32B_X32(r, addr) \
    asm volatile("tcgen05.ld.sync.aligned.32x32b.x32.b32 " \
        "{%0, %1, %2, %3, %4, %5, %6, %7, %8, %9, %10, %11, %12, %13, %14, %15, " \
        " %16, %17, %18, %19, %20, %21, %22, %23, %24, %25, %26, %27, %28, %29, %30, %31}, [%32];" \
        : "=r"((r)[0]),  "=r"((r)[1]),  "=r"((r)[2]),  "=r"((r)[3]), \
          "=r"((r)[4]),  "=r"((r)[5]),  "=r"((r)[6]),  "=r"((r)[7]), \
          "=r"((r)[8]),  "=r"((r)[9]),  "=r"((r)[10]), "=r"((r)[11]), \
          "=r"((r)[12]), "=r"((r)[13]), "=r"((r)[14]), "=r"((r)[15]), \
          "=r"((r)[16]), "=r"((r)[17]), "=r"((r)[18]), "=r"((r)[19]), \
          "=r"((r)[20]), "=r"((r)[21]), "=r"((r)[22]), "=r"((r)[23]), \
          "=r"((r)[24]), "=r"((r)[25]), "=r"((r)[26]), "=r"((r)[27]), \
          "=r"((r)[28]), "=r"((r)[29]), "=r"((r)[30]), "=r"((r)[31]) \
        : "r"(addr))

__device__ __forceinline__ void mma_bf16_ss(uint32_t d, uint64_t a, uint64_t b,
                                            uint32_t idesc, bool acc) {
    uint32_t en = acc ? 1u : 0u;
    asm volatile(
        "{\n\t.reg .pred p;\n\tsetp.ne.u32 p, %5, 0;\n\t"
        "tcgen05.mma.cta_group::1.kind::f16 [%0], %1, %2, %3, {%4, %4, %4, %4}, p;\n\t}"
        :: "r"(d), "l"(a), "l"(b), "r"(idesc), "r"(0u), "r"(en) : "memory");
}
static constexpr uint32_t IDESC_N128 = 0x8200490u;

// Pack 8 fp32 -> 16B hi + 16B lo stores (tile format, matches load/weight path).
__device__ __forceinline__ void store_pack8(uint32_t dsth, uint32_t dstl, const float* v) {
    uint32_t h[4], l[4];
#pragma unroll
    for (int j = 0; j < 4; ++j) {
        uint32_t h0, l0, h1, l1;
        split_bf16(v[2 * j], h0, l0);
        split_bf16(v[2 * j + 1], h1, l1);
        h[j] = h0 | (h1 << 16);
        l[j] = l0 | (l1 << 16);
    }
    asm volatile("st.shared.v4.b32 [%0], {%1,%2,%3,%4};"
                 :: "r"(dsth), "r"(h[0]), "r"(h[1]), "r"(h[2]), "r"(h[3]) : "memory");
    asm volatile("st.shared.v4.b32 [%0], {%1,%2,%3,%4};"
                 :: "r"(dstl), "r"(l[0]), "r"(l[1]), "r"(l[2]), "r"(l[3]) : "memory");
}

// ---------------- one fused layer ----------------
// A tiles resident at SM_A (tile kc = K cols kc*32..+31). B streamed from
// pre-tiled weight images. Epilogue packs output back into A tiles.
// HEAD: 0 none, 1 density->sdens, 2 rgb->srgb (no A-tile write).
template <int NCH, int NT, bool RELU, bool ROWBIAS, int HEAD>
__device__ __forceinline__ void run_layer(
    uint32_t smem_base, uint32_t tmem_base, const uint4* __restrict__ wt,
    const float* __restrict__ bias, const float* __restrict__ rowbias,
    const float* __restrict__ hw, const float* __restrict__ hb,
    int tid, long m0, int& c0, int& c1,
    float* sd, float* sdens, float* srgb)
{
    const int wid = tid >> 5;
    const int lane = tid & 31;

    for (int kc = 0; kc < NCH; ++kc) {
        const int st = kc & 1;
        int& cnt = st ? c1 : c0;
        const uint32_t mb = smem_base + (st ? SM_MB1 : SM_MB0);
        if (cnt > 0) MBARRIER_WAIT_PARITY(mb, (cnt - 1) & 1);

        const uint32_t bstage = smem_base + SM_B + st * 32768;
#pragma unroll
        for (int nh = 0; nh < NT; ++nh) {
            const uint4* src = wt + (size_t)(kc * NT + nh) * 1024 + tid * 4;
            uint32_t dst = bstage + nh * 16384 + tid * 64;
#pragma unroll
            for (int j = 0; j < 4; ++j) {
                uint4 p = src[j];
                asm volatile("st.shared.v4.b32 [%0], {%1,%2,%3,%4};"
                             :: "r"(dst + j * 16), "r"(p.x), "r"(p.y), "r"(p.z), "r"(p.w) : "memory");
            }
        }
        FENCE_PROXY_ASYNC();
        __syncthreads();

        if (wid == 0) {
            if (elect_one_pred()) {
                uint64_t ad = MAKE_SMEM_DESC(smem_base + SM_A + kc * 16384);
#pragma unroll
                for (int nh = 0; nh < NT; ++nh) {
                    uint64_t bd = MAKE_SMEM_DESC(bstage + nh * 16384);
                    uint32_t d = tmem_base + nh * 128;
#pragma unroll
                    for (int ks = 0; ks < 2; ++ks)
                        mma_bf16_ss(d, ad + ks * 2, bd + ks * 2, IDESC_N128, !(kc == 0 && ks == 0));
#pragma unroll
                    for (int ks = 0; ks < 2; ++ks)
                        mma_bf16_ss(d, ad + 4 + ks * 2, bd + ks * 2, IDESC_N128, true);
#pragma unroll
                    for (int ks = 0; ks < 2; ++ks)
                        mma_bf16_ss(d, ad + ks * 2, bd + 4 + ks * 2, IDESC_N128, true);
                }
                TCGEN05_COMMIT(mb);
            }
        }
        cnt++;
    }

    MBARRIER_WAIT_PARITY(smem_base + SM_MB0, (c0 - 1) & 1);
    MBARRIER_WAIT_PARITY(smem_base + SM_MB1, (c1 - 1) & 1);
    TCGEN05_FENCE_AFTER();

    // ---- epilogue ----
    const int wg = wid >> 2;
    const int sub = wid & 3;
    if (NT == 2 || wg == 0) {
        const int row = sub * 32 + lane;
        const long grow = m0 + row;
        const float* rbp = ROWBIAS ? (rowbias + (grow >> 6) * (long)(NT * 128)) : nullptr;
        float dpart = 0.0f, a0 = 0.0f, a1 = 0.0f, a2 = 0.0f;
#pragma unroll
        for (int cb = 0; cb < 4; ++cb) {
            int col0 = wg * 128 + cb * 32;
            uint32_t regs[32];
            TCGEN05_LD_32X32B_X32(regs, tmem_base + col0);
            TCGEN05_WAIT_LD();
            float vals[32];
#pragma unroll
            for (int c = 0; c < 32; ++c) {
                float v = __uint_as_float(regs[c]) + bias[col0 + c];
                if (ROWBIAS) v += rbp[col0 + c];
                if (RELU) v = fmaxf(v, 0.0f);
                if (HEAD == 1) dpart = fmaf(v, hw[col0 + c], dpart);
                if (HEAD == 2) {
                    a0 = fmaf(v, hw[(col0 + c) * 3 + 0], a0);
                    a1 = fmaf(v, hw[(col0 + c) * 3 + 1], a1);
                    a2 = fmaf(v, hw[(col0 + c) * 3 + 2], a2);
                }
                vals[c] = v;
            }
            if (HEAD != 2) {
                uint32_t tb = smem_base + SM_A + (wg * 4 + cb) * 16384;
#pragma unroll
                for (int u = 0; u < 4; ++u)
                    store_pack8(tb + SMEM_SWIZZLE_128B((uint32_t)(row * 128 + u * 16)),
                                tb + SMEM_SWIZZLE_128B((uint32_t)(row * 128 + 64 + u * 16)),
                                vals + u * 8);
            }
        }
        if (HEAD == 1) sd[wg * 128 + row] = dpart;
        if (HEAD == 2) {
            srgb[row * 3 + 0] = 1.0f / (1.0f + expf(-(a0 + hb[0])));
            srgb[row * 3 + 1] = 1.0f / (1.0f + expf(-(a1 + hb[1])));
            srgb[row * 3 + 2] = 1.0f / (1.0f + expf(-(a2 + hb[2])));
        }
    }
    if (HEAD == 1) {
        __syncthreads();
        if (tid < 128) sdens[tid] = sd[tid] + sd[128 + tid] + hb[0];
    }
    TCGEN05_FENCE_BEFORE();
    FENCE_PROXY_ASYNC();
    __syncthreads();
}
#endif  // HAS_TCGEN05

// ---------------- the fused renderer kernel ----------------
__global__ void __launch_bounds__(256)
fused_kernel(const float* __restrict__ xyz,
             const float* __restrict__ b1, const float* __restrict__ b2,
             const float* __restrict__ b3,
             const float* __restrict__ Wsig, const float* __restrict__ bsig,
             const float* __restrict__ bfeat, const float* __restrict__ bdir,
             const float* __restrict__ Wrgb, const float* __restrict__ brgb,
             const float* __restrict__ W1, const float* __restrict__ W2,
             const float* __restrict__ W3, const float* __restrict__ Wfeat,
             const float* __restrict__ Wdir,
             float* __restrict__ out)
{
    extern __shared__ char smem[];
    const int tid = threadIdx.x;
    const long m0 = (long)blockIdx.x * 128;
#if HAS_TCGEN05
    const uint32_t smem_base = smem_to_u32(smem);
    const int wid = tid >> 5;
    float* sd    = reinterpret_cast<float*>(smem + SM_SD);
    float* srgb  = reinterpret_cast<float*>(smem + SM_RGB);
    float* sdens = reinterpret_cast<float*>(smem + SM_DENS);

    if (wid == 0) TCGEN05_ALLOC(smem_base + SM_TM, 256);
    __syncthreads();
    uint32_t tmem_base;
    asm volatile("ld.shared.b32 %0, [%1];" : "=r"(tmem_base) : "r"(smem_base + SM_TM));
    if (tid == 0) {
        MBARRIER_INIT(smem_base + SM_MB0, 1);
        MBARRIER_INIT(smem_base + SM_MB1, 1);
    }
    __syncthreads();

    // ---- posenc directly into A tiles 0,1 (K = 64) ----
    {
        int row = tid >> 1;
        int half = tid & 1;
        long grow = m0 + row;
        int ray = (int)(grow >> 6);
        int s = (int)(grow & 63);
        float t = (float)s * (1.0f / 63.0f);
        float sm = NEAR_F * (1.0f - t) + FAR_F * t;
        float p[3];
#pragma unroll
        for (int c = 0; c < 3; ++c)
            p[c] = fmaf(sm, g_vd[ray * 3 + c], xyz[ray * 3 + c]);
        float vals[32];
#pragma unroll
        for (int j = 0; j < 32; ++j) {
            int c = half * 32 + j;
            float val;
            if (c < 3) val = p[c];
            else if (c == 63) val = 0.0f;
            else {
                int q = c - 3, l = q / 6, r = q % 6;
                float ang = p[(r < 3) ? r : r - 3] * (float)(1 << l);
                val = (r < 3) ? sinf(ang) : cosf(ang);
            }
            vals[j] = val;
        }
        uint32_t tb = smem_base + SM_A + half * 16384;
#pragma unroll
        for (int u = 0; u < 4; ++u)
            store_pack8(tb + SMEM_SWIZZLE_128B((uint32_t)(row * 128 + u * 16)),
                        tb + SMEM_SWIZZLE_128B((uint32_t)(row * 128 + 64 + u * 16)),
                        vals + u * 8);
    }
    FENCE_PROXY_ASYNC();
    __syncthreads();

    int c0 = 0, c1 = 0;
    run_layer<2, 2, true,  false, 0>(smem_base, tmem_base, g_w1tile, b1,   nullptr, nullptr, nullptr, tid, m0, c0, c1, sd, sdens, srgb);
    run_layer<8, 2, true,  false, 0>(smem_base, tmem_base, g_w2tile, b2,   nullptr, nullptr, nullptr, tid, m0, c0, c1, sd, sdens, srgb);
    run_layer<8, 2, true,  false, 1>(smem_base, tmem_base, g_w3tile, b3,   nullptr, Wsig,    bsig,    tid, m0, c0, c1, sd, sdens, srgb);
    run_layer<8, 2, false, false, 0>(smem_base, tmem_base, g_wftile, bfeat,nullptr, nullptr, nullptr, tid, m0, c0, c1, sd, sdens, srgb);
    run_layer<8, 1, true,  true,  2>(smem_base, tmem_base, g_wdtile, bdir, g_det,   Wrgb,    brgb,    tid, m0, c0, c1, sd, sdens, srgb);

    // ---- in-kernel volume rendering: this tile = 2 complete rays ----
    if (tid < 2) {
        int ray = (int)(m0 >> 6) + tid;
        float T = 1.0f, r0 = 0.0f, r1 = 0.0f, r2 = 0.0f, depth = 0.0f, asum = 0.0f;
        for (int i = 0; i < NSAMP; ++i) {
            int p = tid * 64 + i;
            float ti = (float)i * (1.0f / 63.0f);
            float sm = NEAR_F * (1.0f - ti) + FAR_F * ti;
            float delta;
            if (i < NSAMP - 1) {
                float tn = (float)(i + 1) * (1.0f / 63.0f);
                delta = (NEAR_F * (1.0f - tn) + FAR_F * tn) - sm;
            } else {
                delta = 1e10f;
            }
            float sigma = fmaxf(sdens[p], 0.0f);
            float alpha = 1.0f - expf(-sigma * delta);
            float w = T * alpha;
            r0 += w * srgb[p * 3 + 0];
            r1 += w * srgb[p * 3 + 1];
            r2 += w * srgb[p * 3 + 2];
            depth += w * sm;
            asum += w;
            T *= (1.0f - alpha);
        }
        float bk = 1.0f - asum;
        out[ray * 3 + 0] = r0 + bk;
        out[ray * 3 + 1] = r1 + bk;
        out[ray * 3 + 2] = r2 + bk;
        out[R_RAYS * 3 + ray] = depth;
        out[R_RAYS * 4 + ray] = asum;
    }

    __syncthreads();
    if (wid == 0) {
        if (elect_one_pred()) {
            MBARRIER_INVAL(smem_base + SM_MB0);
            MBARRIER_INVAL(smem_base + SM_MB1);
        }
        TCGEN05_DEALLOC(tmem_base, 256);
    }
#else
    // ---------- scalar fallback (non-'a' device passes only; correct, slow) ----------
    float* sdens = reinterpret_cast<float*>(smem);
    float* srgb  = sdens + 128;
    if (tid < 128) {
        long grow = m0 + tid;
        int ray = (int)(grow >> 6);
        int s = (int)(grow & 63);
        float t = (float)s * (1.0f / 63.0f);
        float sm = NEAR_F * (1.0f - t) + FAR_F * t;
        float p[3];
        for (int c = 0; c < 3; ++c)
            p[c] = fmaf(sm, g_vd[ray * 3 + c], xyz[ray * 3 + c]);
        float pe[PE_P];
        pe[0] = p[0]; pe[1] = p[1]; pe[2] = p[2];
        float f = 1.0f;
        for (int l = 0; l < 10; ++l) {
            for (int c = 0; c < 3; ++c) {
                float sn, cs;
                sincosf(p[c] * f, &sn, &cs);
                pe[3 + l * 6 + c] = sn;
                pe[3 + l * 6 + 3 + c] = cs;
            }
            f *= 2.0f;
        }
        float a[256], b[256];
        for (int n = 0; n < 256; ++n) {
            float acc = b1[n];
            for (int k = 0; k < PE_P; ++k) acc = fmaf(pe[k], W1[(size_t)k * 256 + n], acc);
            a[n] = fmaxf(acc, 0.0f);
        }
        for (int n = 0; n < 256; ++n) {
            float acc = b2[n];
            for (int k = 0; k < 256; ++k) acc = fmaf(a[k], W2[(size_t)k * 256 + n], acc);
            b[n] = fmaxf(acc, 0.0f);
        }
        for (int n = 0; n < 256; ++n) {
            float acc = b3[n];
            for (int k = 0; k < 256; ++k) acc = fmaf(b[k], W3[(size_t)k * 256 + n], acc);
            a[n] = fmaxf(acc, 0.0f);
        }
        float dens = bsig[0];
        for (int k = 0; k < 256; ++k) dens = fmaf(a[k], Wsig[k], dens);
        for (int n = 0; n < 256; ++n) {
            float acc = bfeat[n];
            for (int k = 0; k < 256; ++k) acc = fmaf(a[k], Wfeat[(size_t)k * 256 + n], acc);
            b[n] = acc;
        }
        float de[PE_D];
        {
            float vx = g_vd[ray * 3 + 0], vy = g_vd[ray * 3 + 1], vz = g_vd[ray * 3 + 2];
            de[0] = vx; de[1] = vy; de[2] = vz;
            float v3[3] = {vx, vy, vz};
            float ff = 1.0f;
            for (int l = 0; l < 4; ++l) {
                for (int c = 0; c < 3; ++c) {
                    float sn, cs;
                    sincosf(v3[c] * ff, &sn, &cs);
                    de[3 + l * 6 + c] = sn;
                    de[3 + l * 6 + 3 + c] = cs;
                }
                ff *= 2.0f;
            }
        }
        float hd[128];
        for (int n = 0; n < 128; ++n) {
            float acc = bdir[n];
            for (int k = 0; k < 256; ++k) acc = fmaf(b[k], Wdir[(size_t)k * 128 + n], acc);
            for (int k = 0; k < PE_D; ++k) acc = fmaf(de[k], Wdir[(size_t)(256 + k) * 128 + n], acc);
            hd[n] = fmaxf(acc, 0.0f);
        }
        for (int c = 0; c < 3; ++c) {
            float acc = brgb[c];
            for (int k = 0; k < 128; ++k) acc = fmaf(hd[k], Wrgb[k * 3 + c], acc);
            srgb[tid * 3 + c] = 1.0f / (1.0f + expf(-acc));
        }
        sdens[tid] = dens;
    }
    __syncthreads();
    if (tid < 2) {
        int ray = (int)(m0 >> 6) + tid;
        float T = 1.0f, r0 = 0.0f, r1 = 0.0f, r2 = 0.0f, depth = 0.0f, asum = 0.0f;
        for (int i = 0; i < NSAMP; ++i) {
            int p = tid * 64 + i;
            float ti = (float)i * (1.0f / 63.0f);
            float sm = NEAR_F * (1.0f - ti) + FAR_F * ti;
            float delta = (i < NSAMP - 1) ? ((FAR_F - NEAR_F) / 63.0f) : 1e10f;
            float sigma = fmaxf(sdens[p], 0.0f);
            float alpha = 1.0f - expf(-sigma * delta);
            float w = T * alpha;
            r0 += w * srgb[p * 3 + 0];
            r1 += w * srgb[p * 3 + 1];
            r2 += w * srgb[p * 3 + 2];
            depth += w * sm;
            asum += w;
            T *= (1.0f - alpha);
        }
        float bk = 1.0f - asum;
        out[ray * 3 + 0] = r0 + bk;
        out[ray * 3 + 1] = r1 + bk;
        out[ray * 3 + 2] = r2 + bk;
        out[R_RAYS * 3 + ray] = depth;
        out[R_RAYS * 4 + ray] = asum;
    }
#endif
}

// ---------------- host launch ----------------
extern "C" void kernel_launch(void* const* d_in, const int* in_sizes, int n_in,
                              void* d_out, int out_size) {
    const float* xyz      = (const float*)d_in[0];
    const float* viewdirs = (const float*)d_in[1];
    const float* W1   = (const float*)d_in[2];
    const float* b1   = (const float*)d_in[3];
    const float* W2   = (const float*)d_in[4];
    const float* b2   = (const float*)d_in[5];
    const float* W3   = (const float*)d_in[6];
    const float* b3   = (const float*)d_in[7];
    const float* Wsig = (const float*)d_in[8];
    const float* bsig = (const float*)d_in[9];
    const float* Wfeat= (const float*)d_in[10];
    const float* bfeat= (const float*)d_in[11];
    const float* Wdir = (const float*)d_in[12];
    const float* bdir = (const float*)d_in[13];
    const float* Wrgb = (const float*)d_in[14];
    const float* brgb = (const float*)d_in[15];
    float* out = (float*)d_out;

    uint4 *w1t, *w2t, *w3t, *wft, *wdt;
    cudaGetSymbolAddress((void**)&w1t, g_w1tile);
    cudaGetSymbolAddress((void**)&w2t, g_w2tile);
    cudaGetSymbolAddress((void**)&w3t, g_w3tile);
    cudaGetSymbolAddress((void**)&wft, g_wftile);
    cudaGetSymbolAddress((void**)&wdt, g_wdtile);

    cudaFuncSetAttribute(fused_kernel, cudaFuncAttributeMaxDynamicSharedMemorySize, SMEM_TOTAL);

    // ---- prep ----
    prep_rays_kernel<<<R_RAYS / 256, 256>>>(viewdirs);
    de_term_kernel<<<R_RAYS * DHD / 256, 256>>>(Wdir);
    tile_weight_kernel<<<(2 * 2 * 512 + 255) / 256, 256>>>(W1,   w1t, PE_P,  D_HID, 2, 2);
    tile_weight_kernel<<<(8 * 2 * 512 + 255) / 256, 256>>>(W2,   w2t, D_HID, D_HID, 2, 8);
    tile_weight_kernel<<<(8 * 2 * 512 + 255) / 256, 256>>>(W3,   w3t, D_HID, D_HID, 2, 8);
    tile_weight_kernel<<<(8 * 2 * 512 + 255) / 256, 256>>>(Wfeat,wft, D_HID, D_HID, 2, 8);
    tile_weight_kernel<<<(8 * 1 * 512 + 255) / 256, 256>>>(Wdir, wdt, D_HID, DHD,   1, 8);

    // ---- fully fused pipeline: posenc -> 5 MMA layers -> heads -> composite ----
    fused_kernel<<<NPTS / 128, 256, SMEM_TOTAL>>>(
        xyz, b1, b2, b3, Wsig, bsig, bfeat, bdir, Wrgb, brgb,
        W1, W2, W3, Wfeat, Wdir, out);
}

// round 14
// speedup vs baseline: 3.4848x; 1.4136x over previous
#include <cuda_runtime.h>
#include <cuda_bf16.h>
#include <math.h>
#include <stdint.h>

// ---------------- problem constants ----------------
#define R_RAYS   4096
#define NSAMP    64
#define NPTS     (R_RAYS * NSAMP)   // 262144
#define D_HID    256
#define DHD      128
#define PE_P     63
#define PE_PAD   64
#define PE_D     27
#define NEAR_F   2.0f
#define FAR_F    6.0f

// ---- arch-specific feature gate (tcgen05 only legal in sm_103a/..a passes) ----
#if defined(__CUDA_ARCH__) && \
    (defined(__CUDA_ARCH_FEAT_SM103_ALL) || defined(__CUDA_ARCH_FEAT_SM100_ALL) || \
     defined(__CUDA_ARCH_SPECIFIC__) || defined(__CUDA_ARCH_FAMILY_SPECIFIC__))
#define HAS_TCGEN05 1
#else
#define HAS_TCGEN05 0
#endif

// ---------------- device scratch (static, allowed) ----------------
__device__ float g_vd[R_RAYS * 3];
__device__ float g_det[R_RAYS * DHD];
// Pre-tiled weights: each tile is a 16KB SW128 image (hi bf16 bytes [0,64),
// lo bf16 bytes [64,128) per 128B row), laid out [NCH][NT][1024 uint4].
__device__ uint4 g_w1tile[2 * 2 * 1024];
__device__ uint4 g_w2tile[8 * 2 * 1024];
__device__ uint4 g_w3tile[8 * 2 * 1024];
__device__ uint4 g_wftile[8 * 2 * 1024];
__device__ uint4 g_wdtile[8 * 1 * 1024];

#define SMEM_SWIZZLE_128B(off) ((off) ^ (((off) >> 3) & 0x70))

// smem layout (fused kernel)
#define SM_TM    0
#define SM_MB0   8      // commit (stage empty) barriers
#define SM_MB1   16
#define SM_MBF0  24     // TMA full barriers
#define SM_MBF1  32
#define SM_SD    64                    // 256 floats (density partial)
#define SM_RGB   1088                  // 384 floats
#define SM_DENS  2624                  // 128 floats
#define SM_A     4096                  // 8 x 16KB A tiles
#define SM_B     (4096 + 8 * 16384)    // 2 stages x 32KB
#define SMEM_TOTAL (SM_B + 2 * 32768)  // 200704

// ---------------- bf16 split helpers ----------------
__device__ __forceinline__ void split_bf16(float v, uint32_t& h, uint32_t& l) {
    __nv_bfloat16 hb = __float2bfloat16_rn(v);
    float hf = __bfloat162float(hb);
    __nv_bfloat16 lb = __float2bfloat16_rn(v - hf);
    h = (uint32_t)__bfloat16_as_ushort(hb);
    l = (uint32_t)__bfloat16_as_ushort(lb);
}

// ---------------- small prep kernels ----------------
__global__ void prep_rays_kernel(const float* __restrict__ viewdirs) {
    int r = blockIdx.x * blockDim.x + threadIdx.x;
    if (r >= R_RAYS) return;
    float vx = viewdirs[r * 3 + 0], vy = viewdirs[r * 3 + 1], vz = viewdirs[r * 3 + 2];
    float inv = 1.0f / sqrtf(vx * vx + vy * vy + vz * vz);
    g_vd[r * 3 + 0] = vx * inv; g_vd[r * 3 + 1] = vy * inv; g_vd[r * 3 + 2] = vz * inv;
}

// de_term[r, n] = sum_k de[r,k] * Wdir[256+k, n]   (concat tail of dir layer)
__global__ void de_term_kernel(const float* __restrict__ Wdir) {
    int t = blockIdx.x * blockDim.x + threadIdx.x;
    int r = t >> 7;
    int n = t & 127;
    float vx = g_vd[r * 3 + 0], vy = g_vd[r * 3 + 1], vz = g_vd[r * 3 + 2];
    float de[PE_D];
    de[0] = vx; de[1] = vy; de[2] = vz;
    float v[3] = {vx, vy, vz};
    float f = 1.0f;
#pragma unroll
    for (int l = 0; l < 4; ++l) {
#pragma unroll
        for (int c = 0; c < 3; ++c) {
            float sn, cs;
            sincosf(v[c] * f, &sn, &cs);
            de[3 + l * 6 + c] = sn;
            de[3 + l * 6 + 3 + c] = cs;
        }
        f *= 2.0f;
    }
    float s = 0.0f;
#pragma unroll
    for (int k = 0; k < PE_D; ++k)
        s = fmaf(de[k], Wdir[(size_t)(D_HID + k) * DHD + n], s);
    g_det[(size_t)r * DHD + n] = s;
}

// Build 16KB SW128 weight-tile images from W [K_in x N] (row-major, fp32).
__global__ void tile_weight_kernel(const float* __restrict__ W, uint4* __restrict__ tiles,
                                   int K_in, int N, int NT, int NCH) {
    int idx = blockIdx.x * blockDim.x + threadIdx.x;
    int total = NCH * NT * 512;
    if (idx >= total) return;
    int g = idx & 3;
    int row = (idx >> 2) & 127;
    int rest = idx >> 9;
    int nh = rest % NT;
    int kc = rest / NT;
    int n = nh * 128 + row;
    uint32_t h[4], l[4];
#pragma unroll
    for (int j = 0; j < 4; ++j) {
        uint32_t h0, l0, h1, l1;
        int k0 = kc * 32 + g * 8 + 2 * j;
        float v0 = (k0 < K_in) ? W[(size_t)k0 * N + n] : 0.0f;
        float v1 = (k0 + 1 < K_in) ? W[(size_t)(k0 + 1) * N + n] : 0.0f;
        split_bf16(v0, h0, l0);
        split_bf16(v1, h1, l1);
        h[j] = h0 | (h1 << 16);
        l[j] = l0 | (l1 << 16);
    }
    uint4* tb = tiles + (size_t)(kc * NT + nh) * 1024;
    uint32_t offh = SMEM_SWIZZLE_128B((uint32_t)(row * 128 + g * 16));
    uint32_t offl = SMEM_SWIZZLE_128B((uint32_t)(row * 128 + 64 + g * 16));
    tb[offh >> 4] = make_uint4(h[0], h[1], h[2], h[3]);
    tb[offl >> 4] = make_uint4(l[0], l[1], l[2], l[3]);
}

#if HAS_TCGEN05
// ---------------- PTX helpers (from verified sm_103a examples) ----------------
__device__ __forceinline__ uint32_t smem_to_u32(const void* p) {
    uint32_t a;
    asm("{ .reg .u64 t; cvta.to.shared.u64 t, %1; cvt.u32.u64 %0, t; }" : "=r"(a) : "l"(p));
    return a;
}
__device__ __forceinline__ uint32_t elect_one_pred() {
    uint32_t pred;
    asm volatile("{\n\t.reg .pred p;\n\telect.sync _|p, 0xFFFFFFFF;\n\tselp.b32 %0, 1, 0, p;\n\t}"
                 : "=r"(pred));
    return pred;
}
static constexpr uint64_t SMEM_DESC_BASE_SW128 =
    (uint64_t(2) << 61) | (uint64_t(1) << 46) | (uint64_t(64) << 32) | (uint64_t(1) << 16);
#define MAKE_SMEM_DESC(addr) (SMEM_DESC_BASE_SW128 | ((uint64_t)((addr) >> 4) & 0x3FFF))

#define FENCE_PROXY_ASYNC() \
    asm volatile("fence.proxy.async.shared::cta;" ::: "memory")

#define MBARRIER_INIT(mbar, cnt) \
    asm volatile("mbarrier.init.shared.b64 [%0], %1;" :: "r"((uint32_t)(mbar)), "r"((uint32_t)(cnt)) : "memory")
#define MBARRIER_INVAL(mbar) \
    asm volatile("mbarrier.inval.shared.b64 [%0];" :: "r"((uint32_t)(mbar)) : "memory")
#define MBARRIER_EXPECT_TX(mbar, bytes) \
    asm volatile("mbarrier.arrive.expect_tx.shared.b64 _, [%0], %1;" \
                 :: "r"((uint32_t)(mbar)), "r"((uint32_t)(bytes)) : "memory")
#define MBARRIER_WAIT_PARITY(mbar, par) do {                                        \
    uint32_t _m = (uint32_t)(mbar); uint32_t _p = (uint32_t)(par); uint32_t _d;     \
    asm volatile("{\n\t.reg .pred p;\n\t"                                           \
        "mbarrier.try_wait.parity.acquire.cta.shared::cta.b64 p, [%1], %2;\n\t"     \
        "selp.b32 %0, 1, 0, p;\n\t}" : "=r"(_d) : "r"(_m), "r"(_p) : "memory");     \
    if (!_d) {                                                                      \
        asm volatile("{\n\t.reg .pred P1;\n\t"                                      \
            "WAIT_LOOP_%=:\n\t"                                                     \
            "mbarrier.try_wait.parity.acquire.cta.shared::cta.b64 P1, [%0], %1, 0x989680;\n\t" \
            "@P1 bra.uni WAIT_DONE_%=;\n\t"                                         \
            "bra.uni WAIT_LOOP_%=;\n\t"                                             \
            "WAIT_DONE_%=:\n\t}" :: "r"(_m), "r"(_p) : "memory");                   \
    }                                                                               \
} while (0)

// 1D bulk async copy gmem -> smem, tx-completing on mbar (SASS: UBLKCP).
#define TMA_BULK_G2S(dst, src, bytes, mbar) \
    asm volatile("cp.async.bulk.shared::cta.global.mbarrier::complete_tx::bytes [%0], [%1], %2, [%3];" \
                 :: "r"((uint32_t)(dst)), "l"(src), "r"((uint32_t)(bytes)), "r"((uint32_t)(mbar)) : "memory")

#define TCGEN05_ALLOC(res, n) \
    asm volatile("tcgen05.alloc.cta_group::1.sync.aligned.shared::cta.b32 [%0], %1;" \
                 :: "r"((uint32_t)(res)), "r"((uint32_t)(n)) : "memory")
#define TCGEN05_DEALLOC(addr, n) \
    asm volatile("tcgen05.dealloc.cta_group::1.sync.aligned.b32 %0, %1;" :: "r"(addr), "r"((uint32_t)(n)))
#define TCGEN05_COMMIT(mbar) \
    asm volatile("tcgen05.commit.cta_group::1.mbarrier::arrive::one.shared::cluster.b64 [%0];" \
                 :: "r"((uint32_t)(mbar)) : "memory")
#define TCGEN05_WAIT_LD()  asm volatile("tcgen05.wait::ld.sync.aligned;" ::: "memory")
#define TCGEN05_FENCE_AFTER()  asm volatile("tcgen05.fence::after_thread_sync;" ::: "memory")
#define TCGEN05_FENCE_BEFORE() asm volatile("tcgen05.fence::before_thread_sync;" ::: "memory")

#define TCGEN05_LD_32X32B_X32(r, addr) \
    asm volatile("tcgen05.ld.sync.aligned.32x32b.x32.b32 " \
        "{%0, %1, %2, %3, %4, %5, %6, %7, %8, %9, %10, %11, %12, %13, %14, %15, " \
        " %16, %17, %18, %19, %20, %21, %22, %23, %24, %25, %26, %27, %28, %29, %30, %31}, [%32];" \
        : "=r"((r)[0]),  "=r"((r)[1]),  "=r"((r)[2]),  "=r"((r)[3]), \
          "=r"((r)[4]),  "=r"((r)[5]),  "=r"((r)[6]),  "=r"((r)[7]), \
          "=r"((r)[8]),  "=r"((r)[9]),  "=r"((r)[10]), "=r"((r)[11]), \
          "=r"((r)[12]), "=r"((r)[13]), "=r"((r)[14]), "=r"((r)[15]), \
          "=r"((r)[16]), "=r"((r)[17]), "=r"((r)[18]), "=r"((r)[19]), \
          "=r"((r)[20]), "=r"((r)[21]), "=r"((r)[22]), "=r"((r)[23]), \
          "=r"((r)[24]), "=r"((r)[25]), "=r"((r)[26]), "=r"((r)[27]), \
          "=r"((r)[28]), "=r"((r)[29]), "=r"((r)[30]), "=r"((r)[31]) \
        : "r"(addr))

__device__ __forceinline__ void mma_bf16_ss(uint32_t d, uint64_t a, uint64_t b,
                                            uint32_t idesc, bool acc) {
    uint32_t en = acc ? 1u : 0u;
    asm volatile(
        "{\n\t.reg .pred p;\n\tsetp.ne.u32 p, %5, 0;\n\t"
        "tcgen05.mma.cta_group::1.kind::f16 [%0], %1, %2, %3, {%4, %4, %4, %4}, p;\n\t}"
        :: "r"(d), "l"(a), "l"(b), "r"(idesc), "r"(0u), "r"(en) : "memory");
}
static constexpr uint32_t IDESC_N128 = 0x8200490u;

// Pack 8 fp32 -> 16B hi + 16B lo stores (tile format, matches load/weight path).
__device__ __forceinline__ void store_pack8(uint32_t dsth, uint32_t dstl, const float* v) {
    uint32_t h[4], l[4];
#pragma unroll
    for (int j = 0; j < 4; ++j) {
        uint32_t h0, l0, h1, l1;
        split_bf16(v[2 * j], h0, l0);
        split_bf16(v[2 * j + 1], h1, l1);
        h[j] = h0 | (h1 << 16);
        l[j] = l0 | (l1 << 16);
    }
    asm volatile("st.shared.v4.b32 [%0], {%1,%2,%3,%4};"
                 :: "r"(dsth), "r"(h[0]), "r"(h[1]), "r"(h[2]), "r"(h[3]) : "memory");
    asm volatile("st.shared.v4.b32 [%0], {%1,%2,%3,%4};"
                 :: "r"(dstl), "r"(l[0]), "r"(l[1]), "r"(l[2]), "r"(l[3]) : "memory");
}

// ---------------- one fused layer (TMA producer + single orchestrator) ----------------
// A tiles resident at SM_A. B streamed by ONE thread (tid 0) via cp.async.bulk
// into a 2-stage ring; the same thread issues MMAs and is the ONLY thread that
// ever waits on the pipeline mbarriers (parity waits are only unambiguous for
// a phase-synchronous waiter). Completion is published to the other threads by
// __syncthreads AFTER tid 0's final drain waits.
// HEAD: 0 none, 1 density->sdens, 2 rgb->srgb (no A-tile write).
template <int NCH, int NT, bool RELU, bool ROWBIAS, int HEAD>
__device__ __forceinline__ void run_layer(
    uint32_t smem_base, uint32_t tmem_base, const uint4* __restrict__ wt,
    const float* __restrict__ bias, const float* __restrict__ rowbias,
    const float* __restrict__ hw, const float* __restrict__ hb,
    int tid, long m0, int& c0, int& c1, int& f0, int& f1,
    float* sd, float* sdens, float* srgb)
{
    const int wid = tid >> 5;
    const int lane = tid & 31;

    if (tid == 0) {
        for (int kc = 0; kc < NCH; ++kc) {
            const int st = kc & 1;
            int& cnt = st ? c1 : c0;
            int& ftx = st ? f1 : f0;
            const uint32_t cmb = smem_base + (st ? SM_MB1 : SM_MB0);
            const uint32_t fmb = smem_base + (st ? SM_MBF1 : SM_MBF0);
            // stage empty = MMAs that last read this stage have committed
            if (cnt > 0) MBARRIER_WAIT_PARITY(cmb, (cnt - 1) & 1);
            const uint32_t bstage = smem_base + SM_B + st * 32768;
            MBARRIER_EXPECT_TX(fmb, NT * 16384);
            // tiles for one kc are contiguous in gmem: single bulk copy
            TMA_BULK_G2S(bstage, (const void*)(wt + (size_t)kc * NT * 1024),
                         NT * 16384, fmb);
            MBARRIER_WAIT_PARITY(fmb, ftx & 1);
            ftx++;
            uint64_t ad = MAKE_SMEM_DESC(smem_base + SM_A + kc * 16384);
#pragma unroll
            for (int nh = 0; nh < NT; ++nh) {
                uint64_t bd = MAKE_SMEM_DESC(bstage + nh * 16384);
                uint32_t d = tmem_base + nh * 128;
#pragma unroll
                for (int ks = 0; ks < 2; ++ks)
                    mma_bf16_ss(d, ad + ks * 2, bd + ks * 2, IDESC_N128, !(kc == 0 && ks == 0));
#pragma unroll
                for (int ks = 0; ks < 2; ++ks)
                    mma_bf16_ss(d, ad + 4 + ks * 2, bd + ks * 2, IDESC_N128, true);
#pragma unroll
                for (int ks = 0; ks < 2; ++ks)
                    mma_bf16_ss(d, ad + ks * 2, bd + 4 + ks * 2, IDESC_N128, true);
            }
            TCGEN05_COMMIT(cmb);
            cnt++;
        }
        // final drain — tid 0 is phase-synchronous (lag <= 1 phase per barrier)
        if (c0 > 0) MBARRIER_WAIT_PARITY(smem_base + SM_MB0, (c0 - 1) & 1);
        if (c1 > 0) MBARRIER_WAIT_PARITY(smem_base + SM_MB1, (c1 - 1) & 1);
    } else {
        // keep counters consistent across layers (no mbarrier access!)
        c0 += (NCH + 1) / 2;  c1 += NCH / 2;
        f0 += (NCH + 1) / 2;  f1 += NCH / 2;
    }

    // publish MMA completion (established by tid 0) to all threads
    __syncthreads();
    TCGEN05_FENCE_AFTER();

    // ---- epilogue ----
    const int wg = wid >> 2;
    const int sub = wid & 3;
    if (NT == 2 || wg == 0) {
        const int row = sub * 32 + lane;
        const long grow = m0 + row;
        const float* rbp = ROWBIAS ? (rowbias + (grow >> 6) * (long)(NT * 128)) : nullptr;
        float dpart = 0.0f, a0 = 0.0f, a1 = 0.0f, a2 = 0.0f;
#pragma unroll
        for (int cb = 0; cb < 4; ++cb) {
            int col0 = wg * 128 + cb * 32;
            uint32_t regs[32];
            TCGEN05_LD_32X32B_X32(regs, tmem_base + col0);
            TCGEN05_WAIT_LD();
            float vals[32];
#pragma unroll
            for (int c = 0; c < 32; ++c) {
                float v = __uint_as_float(regs[c]) + bias[col0 + c];
                if (ROWBIAS) v += rbp[col0 + c];
                if (RELU) v = fmaxf(v, 0.0f);
                if (HEAD == 1) dpart = fmaf(v, hw[col0 + c], dpart);
                if (HEAD == 2) {
                    a0 = fmaf(v, hw[(col0 + c) * 3 + 0], a0);
                    a1 = fmaf(v, hw[(col0 + c) * 3 + 1], a1);
                    a2 = fmaf(v, hw[(col0 + c) * 3 + 2], a2);
                }
                vals[c] = v;
            }
            if (HEAD != 2) {
                uint32_t tb = smem_base + SM_A + (wg * 4 + cb) * 16384;
#pragma unroll
                for (int u = 0; u < 4; ++u)
                    store_pack8(tb + SMEM_SWIZZLE_128B((uint32_t)(row * 128 + u * 16)),
                                tb + SMEM_SWIZZLE_128B((uint32_t)(row * 128 + 64 + u * 16)),
                                vals + u * 8);
            }
        }
        if (HEAD == 1) sd[wg * 128 + row] = dpart;
        if (HEAD == 2) {
            srgb[row * 3 + 0] = 1.0f / (1.0f + expf(-(a0 + hb[0])));
            srgb[row * 3 + 1] = 1.0f / (1.0f + expf(-(a1 + hb[1])));
            srgb[row * 3 + 2] = 1.0f / (1.0f + expf(-(a2 + hb[2])));
        }
    }
    if (HEAD == 1) {
        __syncthreads();
        if (tid < 128) sdens[tid] = sd[tid] + sd[128 + tid] + hb[0];
    }
    TCGEN05_FENCE_BEFORE();
    FENCE_PROXY_ASYNC();
    __syncthreads();
}
#endif  // HAS_TCGEN05

// ---------------- the fused renderer kernel ----------------
__global__ void __launch_bounds__(256)
fused_kernel(const float* __restrict__ xyz,
             const float* __restrict__ b1, const float* __restrict__ b2,
             const float* __restrict__ b3,
             const float* __restrict__ Wsig, const float* __restrict__ bsig,
             const float* __restrict__ bfeat, const float* __restrict__ bdir,
             const float* __restrict__ Wrgb, const float* __restrict__ brgb,
             const float* __restrict__ W1, const float* __restrict__ W2,
             const float* __restrict__ W3, const float* __restrict__ Wfeat,
             const float* __restrict__ Wdir,
             float* __restrict__ out)
{
    extern __shared__ char smem[];
    const int tid = threadIdx.x;
    const long m0 = (long)blockIdx.x * 128;
#if HAS_TCGEN05
    const uint32_t smem_base = smem_to_u32(smem);
    const int wid = tid >> 5;
    float* sd    = reinterpret_cast<float*>(smem + SM_SD);
    float* srgb  = reinterpret_cast<float*>(smem + SM_RGB);
    float* sdens = reinterpret_cast<float*>(smem + SM_DENS);

    if (wid == 0) TCGEN05_ALLOC(smem_base + SM_TM, 256);
    __syncthreads();
    uint32_t tmem_base;
    asm volatile("ld.shared.b32 %0, [%1];" : "=r"(tmem_base) : "r"(smem_base + SM_TM));
    if (tid == 0) {
        MBARRIER_INIT(smem_base + SM_MB0, 1);
        MBARRIER_INIT(smem_base + SM_MB1, 1);
        MBARRIER_INIT(smem_base + SM_MBF0, 1);
        MBARRIER_INIT(smem_base + SM_MBF1, 1);
    }
    __syncthreads();

    // ---- posenc directly into A tiles 0,1 (K = 64) ----
    {
        int row = tid >> 1;
        int half = tid & 1;
        long grow = m0 + row;
        int ray = (int)(grow >> 6);
        int s = (int)(grow & 63);
        float t = (float)s * (1.0f / 63.0f);
        float sm = NEAR_F * (1.0f - t) + FAR_F * t;
        float p[3];
#pragma unroll
        for (int c = 0; c < 3; ++c)
            p[c] = fmaf(sm, g_vd[ray * 3 + c], xyz[ray * 3 + c]);
        float vals[32];
#pragma unroll
        for (int j = 0; j < 32; ++j) {
            int c = half * 32 + j;
            float val;
            if (c < 3) val = p[c];
            else if (c == 63) val = 0.0f;
            else {
                int q = c - 3, l = q / 6, r = q % 6;
                float ang = p[(r < 3) ? r : r - 3] * (float)(1 << l);
                val = (r < 3) ? sinf(ang) : cosf(ang);
            }
            vals[j] = val;
        }
        uint32_t tb = smem_base + SM_A + half * 16384;
#pragma unroll
        for (int u = 0; u < 4; ++u)
            store_pack8(tb + SMEM_SWIZZLE_128B((uint32_t)(row * 128 + u * 16)),
                        tb + SMEM_SWIZZLE_128B((uint32_t)(row * 128 + 64 + u * 16)),
                        vals + u * 8);
    }
    FENCE_PROXY_ASYNC();
    __syncthreads();

    int c0 = 0, c1 = 0, f0 = 0, f1 = 0;
    run_layer<2, 2, true,  false, 0>(smem_base, tmem_base, g_w1tile, b1,   nullptr, nullptr, nullptr, tid, m0, c0, c1, f0, f1, sd, sdens, srgb);
    run_layer<8, 2, true,  false, 0>(smem_base, tmem_base, g_w2tile, b2,   nullptr, nullptr, nullptr, tid, m0, c0, c1, f0, f1, sd, sdens, srgb);
    run_layer<8, 2, true,  false, 1>(smem_base, tmem_base, g_w3tile, b3,   nullptr, Wsig,    bsig,    tid, m0, c0, c1, f0, f1, sd, sdens, srgb);
    run_layer<8, 2, false, false, 0>(smem_base, tmem_base, g_wftile, bfeat,nullptr, nullptr, nullptr, tid, m0, c0, c1, f0, f1, sd, sdens, srgb);
    run_layer<8, 1, true,  true,  2>(smem_base, tmem_base, g_wdtile, bdir, g_det,   Wrgb,    brgb,    tid, m0, c0, c1, f0, f1, sd, sdens, srgb);

    // ---- in-kernel volume rendering: this tile = 2 complete rays ----
    if (tid < 2) {
        int ray = (int)(m0 >> 6) + tid;
        float T = 1.0f, r0 = 0.0f, r1 = 0.0f, r2 = 0.0f, depth = 0.0f, asum = 0.0f;
        for (int i = 0; i < NSAMP; ++i) {
            int p = tid * 64 + i;
            float ti = (float)i * (1.0f / 63.0f);
            float sm = NEAR_F * (1.0f - ti) + FAR_F * ti;
            float delta;
            if (i < NSAMP - 1) {
                float tn = (float)(i + 1) * (1.0f / 63.0f);
                delta = (NEAR_F * (1.0f - tn) + FAR_F * tn) - sm;
            } else {
                delta = 1e10f;
            }
            float sigma = fmaxf(sdens[p], 0.0f);
            float alpha = 1.0f - expf(-sigma * delta);
            float w = T * alpha;
            r0 += w * srgb[p * 3 + 0];
            r1 += w * srgb[p * 3 + 1];
            r2 += w * srgb[p * 3 + 2];
            depth += w * sm;
            asum += w;
            T *= (1.0f - alpha);
        }
        float bk = 1.0f - asum;
        out[ray * 3 + 0] = r0 + bk;
        out[ray * 3 + 1] = r1 + bk;
        out[ray * 3 + 2] = r2 + bk;
        out[R_RAYS * 3 + ray] = depth;
        out[R_RAYS * 4 + ray] = asum;
    }

    __syncthreads();
    if (wid == 0) {
        if (elect_one_pred()) {
            MBARRIER_INVAL(smem_base + SM_MB0);
            MBARRIER_INVAL(smem_base + SM_MB1);
            MBARRIER_INVAL(smem_base + SM_MBF0);
            MBARRIER_INVAL(smem_base + SM_MBF1);
        }
        TCGEN05_DEALLOC(tmem_base, 256);
    }
#else
    // ---------- scalar fallback (non-'a' device passes only; correct, slow) ----------
    float* sdens = reinterpret_cast<float*>(smem);
    float* srgb  = sdens + 128;
    if (tid < 128) {
        long grow = m0 + tid;
        int ray = (int)(grow >> 6);
        int s = (int)(grow & 63);
        float t = (float)s * (1.0f / 63.0f);
        float sm = NEAR_F * (1.0f - t) + FAR_F * t;
        float p[3];
        for (int c = 0; c < 3; ++c)
            p[c] = fmaf(sm, g_vd[ray * 3 + c], xyz[ray * 3 + c]);
        float pe[PE_P];
        pe[0] = p[0]; pe[1] = p[1]; pe[2] = p[2];
        float f = 1.0f;
        for (int l = 0; l < 10; ++l) {
            for (int c = 0; c < 3; ++c) {
                float sn, cs;
                sincosf(p[c] * f, &sn, &cs);
                pe[3 + l * 6 + c] = sn;
                pe[3 + l * 6 + 3 + c] = cs;
            }
            f *= 2.0f;
        }
        float a[256], b[256];
        for (int n = 0; n < 256; ++n) {
            float acc = b1[n];
            for (int k = 0; k < PE_P; ++k) acc = fmaf(pe[k], W1[(size_t)k * 256 + n], acc);
            a[n] = fmaxf(acc, 0.0f);
        }
        for (int n = 0; n < 256; ++n) {
            float acc = b2[n];
            for (int k = 0; k < 256; ++k) acc = fmaf(a[k], W2[(size_t)k * 256 + n], acc);
            b[n] = fmaxf(acc, 0.0f);
        }
        for (int n = 0; n < 256; ++n) {
            float acc = b3[n];
            for (int k = 0; k < 256; ++k) acc = fmaf(b[k], W3[(size_t)k * 256 + n], acc);
            a[n] = fmaxf(acc, 0.0f);
        }
        float dens = bsig[0];
        for (int k = 0; k < 256; ++k) dens = fmaf(a[k], Wsig[k], dens);
        for (int n = 0; n < 256; ++n) {
            float acc = bfeat[n];
            for (int k = 0; k < 256; ++k) acc = fmaf(a[k], Wfeat[(size_t)k * 256 + n], acc);
            b[n] = acc;
        }
        float de[PE_D];
        {
            float vx = g_vd[ray * 3 + 0], vy = g_vd[ray * 3 + 1], vz = g_vd[ray * 3 + 2];
            de[0] = vx; de[1] = vy; de[2] = vz;
            float v3[3] = {vx, vy, vz};
            float ff = 1.0f;
            for (int l = 0; l < 4; ++l) {
                for (int c = 0; c < 3; ++c) {
                    float sn, cs;
                    sincosf(v3[c] * ff, &sn, &cs);
                    de[3 + l * 6 + c] = sn;
                    de[3 + l * 6 + 3 + c] = cs;
                }
                ff *= 2.0f;
            }
        }
        float hd[128];
        for (int n = 0; n < 128; ++n) {
            float acc = bdir[n];
            for (int k = 0; k < 256; ++k) acc = fmaf(b[k], Wdir[(size_t)k * 128 + n], acc);
            for (int k = 0; k < PE_D; ++k) acc = fmaf(de[k], Wdir[(size_t)(256 + k) * 128 + n], acc);
            hd[n] = fmaxf(acc, 0.0f);
        }
        for (int c = 0; c < 3; ++c) {
            float acc = brgb[c];
            for (int k = 0; k < 128; ++k) acc = fmaf(hd[k], Wrgb[k * 3 + c], acc);
            srgb[tid * 3 + c] = 1.0f / (1.0f + expf(-acc));
        }
        sdens[tid] = dens;
    }
    __syncthreads();
    if (tid < 2) {
        int ray = (int)(m0 >> 6) + tid;
        float T = 1.0f, r0 = 0.0f, r1 = 0.0f, r2 = 0.0f, depth = 0.0f, asum = 0.0f;
        for (int i = 0; i < NSAMP; ++i) {
            int p = tid * 64 + i;
            float ti = (float)i * (1.0f / 63.0f);
            float sm = NEAR_F * (1.0f - ti) + FAR_F * ti;
            float delta = (i < NSAMP - 1) ? ((FAR_F - NEAR_F) / 63.0f) : 1e10f;
            float sigma = fmaxf(sdens[p], 0.0f);
            float alpha = 1.0f - expf(-sigma * delta);
            float w = T * alpha;
            r0 += w * srgb[p * 3 + 0];
            r1 += w * srgb[p * 3 + 1];
            r2 += w * srgb[p * 3 + 2];
            depth += w * sm;
            asum += w;
            T *= (1.0f - alpha);
        }
        float bk = 1.0f - asum;
        out[ray * 3 + 0] = r0 + bk;
        out[ray * 3 + 1] = r1 + bk;
        out[ray * 3 + 2] = r2 + bk;
        out[R_RAYS * 3 + ray] = depth;
        out[R_RAYS * 4 + ray] = asum;
    }
#endif
}

// ---------------- host launch ----------------
extern "C" void kernel_launch(void* const* d_in, const int* in_sizes, int n_in,
                              void* d_out, int out_size) {
    const float* xyz      = (const float*)d_in[0];
    const float* viewdirs = (const float*)d_in[1];
    const float* W1   = (const float*)d_in[2];
    const float* b1   = (const float*)d_in[3];
    const float* W2   = (const float*)d_in[4];
    const float* b2   = (const float*)d_in[5];
    const float* W3   = (const float*)d_in[6];
    const float* b3   = (const float*)d_in[7];
    const float* Wsig = (const float*)d_in[8];
    const float* bsig = (const float*)d_in[9];
    const float* Wfeat= (const float*)d_in[10];
    const float* bfeat= (const float*)d_in[11];
    const float* Wdir = (const float*)d_in[12];
    const float* bdir = (const float*)d_in[13];
    const float* Wrgb = (const float*)d_in[14];
    const float* brgb = (const float*)d_in[15];
    float* out = (float*)d_out;

    uint4 *w1t, *w2t, *w3t, *wft, *wdt;
    cudaGetSymbolAddress((void**)&w1t, g_w1tile);
    cudaGetSymbolAddress((void**)&w2t, g_w2tile);
    cudaGetSymbolAddress((void**)&w3t, g_w3tile);
    cudaGetSymbolAddress((void**)&wft, g_wftile);
    cudaGetSymbolAddress((void**)&wdt, g_wdtile);

    cudaFuncSetAttribute(fused_kernel, cudaFuncAttributeMaxDynamicSharedMemorySize, SMEM_TOTAL);

    // ---- prep ----
    prep_rays_kernel<<<R_RAYS / 256, 256>>>(viewdirs);
    de_term_kernel<<<R_RAYS * DHD / 256, 256>>>(Wdir);
    tile_weight_kernel<<<(2 * 2 * 512 + 255) / 256, 256>>>(W1,   w1t, PE_P,  D_HID, 2, 2);
    tile_weight_kernel<<<(8 * 2 * 512 + 255) / 256, 256>>>(W2,   w2t, D_HID, D_HID, 2, 8);
    tile_weight_kernel<<<(8 * 2 * 512 + 255) / 256, 256>>>(W3,   w3t, D_HID, D_HID, 2, 8);
    tile_weight_kernel<<<(8 * 2 * 512 + 255) / 256, 256>>>(Wfeat,wft, D_HID, D_HID, 2, 8);
    tile_weight_kernel<<<(8 * 1 * 512 + 255) / 256, 256>>>(Wdir, wdt, D_HID, DHD,   1, 8);

    // ---- fully fused pipeline: posenc -> 5 MMA layers -> heads -> composite ----
    fused_kernel<<<NPTS / 128, 256, SMEM_TOTAL>>>(
        xyz, b1, b2, b3, Wsig, bsig, bfeat, bdir, Wrgb, brgb,
        W1, W2, W3, Wfeat, Wdir, out);
}

// round 16
// speedup vs baseline: 3.4898x; 1.0014x over previous
#include <cuda_runtime.h>
#include <cuda_bf16.h>
#include <math.h>
#include <stdint.h>

// ---------------- problem constants ----------------
#define R_RAYS   4096
#define NSAMP    64
#define NPTS     (R_RAYS * NSAMP)   // 262144
#define D_HID    256
#define DHD      128
#define PE_P     63
#define PE_PAD   64
#define PE_D     27
#define NEAR_F   2.0f
#define FAR_F    6.0f

// ---- arch-specific feature gate (tcgen05 only legal in sm_103a/..a passes) ----
#if defined(__CUDA_ARCH__) && \
    (defined(__CUDA_ARCH_FEAT_SM103_ALL) || defined(__CUDA_ARCH_FEAT_SM100_ALL) || \
     defined(__CUDA_ARCH_SPECIFIC__) || defined(__CUDA_ARCH_FAMILY_SPECIFIC__))
#define HAS_TCGEN05 1
#else
#define HAS_TCGEN05 0
#endif

// ---------------- device scratch (static, allowed) ----------------
__device__ float g_vd[R_RAYS * 3];
__device__ float g_det[R_RAYS * DHD];
// Pre-tiled weights: each tile is a 16KB SW128 image (hi bf16 bytes [0,64),
// lo bf16 bytes [64,128) per 128B row), laid out [NCH][NT][1024 uint4].
__device__ uint4 g_w1tile[2 * 2 * 1024];
__device__ uint4 g_w2tile[8 * 2 * 1024];
__device__ uint4 g_w3tile[8 * 2 * 1024];
__device__ uint4 g_wftile[8 * 2 * 1024];
__device__ uint4 g_wdtile[8 * 1 * 1024];

#define SMEM_SWIZZLE_128B(off) ((off) ^ (((off) >> 3) & 0x70))

// smem layout (fused kernel)
#define SM_TM    0
#define SM_MB0   8      // commit (stage empty) barriers
#define SM_MB1   16
#define SM_MBF0  24     // TMA full barriers
#define SM_MBF1  32
#define SM_SD    64                    // 256 floats (density partial)
#define SM_RGB   1088                  // 384 floats
#define SM_DENS  2624                  // 128 floats
#define SM_A     4096                  // 8 x 16KB A tiles
#define SM_B     (4096 + 8 * 16384)    // 2 stages x 32KB
#define SMEM_TOTAL (SM_B + 2 * 32768)  // 200704

#define NCHUNKS_TOTAL 34   // 2 + 8 + 8 + 8 + 8

// ---------------- bf16 split helpers ----------------
__device__ __forceinline__ void split_bf16(float v, uint32_t& h, uint32_t& l) {
    __nv_bfloat16 hb = __float2bfloat16_rn(v);
    float hf = __bfloat162float(hb);
    __nv_bfloat16 lb = __float2bfloat16_rn(v - hf);
    h = (uint32_t)__bfloat16_as_ushort(hb);
    l = (uint32_t)__bfloat16_as_ushort(lb);
}

// ---------------- small prep kernels ----------------
__global__ void prep_rays_kernel(const float* __restrict__ viewdirs) {
    int r = blockIdx.x * blockDim.x + threadIdx.x;
    if (r >= R_RAYS) return;
    float vx = viewdirs[r * 3 + 0], vy = viewdirs[r * 3 + 1], vz = viewdirs[r * 3 + 2];
    float inv = 1.0f / sqrtf(vx * vx + vy * vy + vz * vz);
    g_vd[r * 3 + 0] = vx * inv; g_vd[r * 3 + 1] = vy * inv; g_vd[r * 3 + 2] = vz * inv;
}

// de_term[r, n] = sum_k de[r,k] * Wdir[256+k, n]   (concat tail of dir layer)
__global__ void de_term_kernel(const float* __restrict__ Wdir) {
    int t = blockIdx.x * blockDim.x + threadIdx.x;
    int r = t >> 7;
    int n = t & 127;
    float vx = g_vd[r * 3 + 0], vy = g_vd[r * 3 + 1], vz = g_vd[r * 3 + 2];
    float de[PE_D];
    de[0] = vx; de[1] = vy; de[2] = vz;
    float v[3] = {vx, vy, vz};
    float f = 1.0f;
#pragma unroll
    for (int l = 0; l < 4; ++l) {
#pragma unroll
        for (int c = 0; c < 3; ++c) {
            float sn, cs;
            sincosf(v[c] * f, &sn, &cs);
            de[3 + l * 6 + c] = sn;
            de[3 + l * 6 + 3 + c] = cs;
        }
        f *= 2.0f;
    }
    float s = 0.0f;
#pragma unroll
    for (int k = 0; k < PE_D; ++k)
        s = fmaf(de[k], Wdir[(size_t)(D_HID + k) * DHD + n], s);
    g_det[(size_t)r * DHD + n] = s;
}

// Build 16KB SW128 weight-tile images from W [K_in x N] (row-major, fp32).
__global__ void tile_weight_kernel(const float* __restrict__ W, uint4* __restrict__ tiles,
                                   int K_in, int N, int NT, int NCH) {
    int idx = blockIdx.x * blockDim.x + threadIdx.x;
    int total = NCH * NT * 512;
    if (idx >= total) return;
    int g = idx & 3;
    int row = (idx >> 2) & 127;
    int rest = idx >> 9;
    int nh = rest % NT;
    int kc = rest / NT;
    int n = nh * 128 + row;
    uint32_t h[4], l[4];
#pragma unroll
    for (int j = 0; j < 4; ++j) {
        uint32_t h0, l0, h1, l1;
        int k0 = kc * 32 + g * 8 + 2 * j;
        float v0 = (k0 < K_in) ? W[(size_t)k0 * N + n] : 0.0f;
        float v1 = (k0 + 1 < K_in) ? W[(size_t)(k0 + 1) * N + n] : 0.0f;
        split_bf16(v0, h0, l0);
        split_bf16(v1, h1, l1);
        h[j] = h0 | (h1 << 16);
        l[j] = l0 | (l1 << 16);
    }
    uint4* tb = tiles + (size_t)(kc * NT + nh) * 1024;
    uint32_t offh = SMEM_SWIZZLE_128B((uint32_t)(row * 128 + g * 16));
    uint32_t offl = SMEM_SWIZZLE_128B((uint32_t)(row * 128 + 64 + g * 16));
    tb[offh >> 4] = make_uint4(h[0], h[1], h[2], h[3]);
    tb[offl >> 4] = make_uint4(l[0], l[1], l[2], l[3]);
}

#if HAS_TCGEN05
// ---------------- PTX helpers (from verified sm_103a examples) ----------------
__device__ __forceinline__ uint32_t smem_to_u32(const void* p) {
    uint32_t a;
    asm("{ .reg .u64 t; cvta.to.shared.u64 t, %1; cvt.u32.u64 %0, t; }" : "=r"(a) : "l"(p));
    return a;
}
__device__ __forceinline__ uint32_t elect_one_pred() {
    uint32_t pred;
    asm volatile("{\n\t.reg .pred p;\n\telect.sync _|p, 0xFFFFFFFF;\n\tselp.b32 %0, 1, 0, p;\n\t}"
                 : "=r"(pred));
    return pred;
}
static constexpr uint64_t SMEM_DESC_BASE_SW128 =
    (uint64_t(2) << 61) | (uint64_t(1) << 46) | (uint64_t(64) << 32) | (uint64_t(1) << 16);
#define MAKE_SMEM_DESC(addr) (SMEM_DESC_BASE_SW128 | ((uint64_t)((addr) >> 4) & 0x3FFF))

#define FENCE_PROXY_ASYNC() \
    asm volatile("fence.proxy.async.shared::cta;" ::: "memory")

#define MBARRIER_INIT(mbar, cnt) \
    asm volatile("mbarrier.init.shared.b64 [%0], %1;" :: "r"((uint32_t)(mbar)), "r"((uint32_t)(cnt)) : "memory")
#define MBARRIER_INVAL(mbar) \
    asm volatile("mbarrier.inval.shared.b64 [%0];" :: "r"((uint32_t)(mbar)) : "memory")
#define MBARRIER_EXPECT_TX(mbar, bytes) \
    asm volatile("mbarrier.arrive.expect_tx.shared.b64 _, [%0], %1;" \
                 :: "r"((uint32_t)(mbar)), "r"((uint32_t)(bytes)) : "memory")
#define MBARRIER_WAIT_PARITY(mbar, par) do {                                        \
    uint32_t _m = (uint32_t)(mbar); uint32_t _p = (uint32_t)(par); uint32_t _d;     \
    asm volatile("{\n\t.reg .pred p;\n\t"                                           \
        "mbarrier.try_wait.parity.acquire.cta.shared::cta.b64 p, [%1], %2;\n\t"     \
        "selp.b32 %0, 1, 0, p;\n\t}" : "=r"(_d) : "r"(_m), "r"(_p) : "memory");     \
    if (!_d) {                                                                      \
        asm volatile("{\n\t.reg .pred P1;\n\t"                                      \
            "WAIT_LOOP_%=:\n\t"                                                     \
            "mbarrier.try_wait.parity.acquire.cta.shared::cta.b64 P1, [%0], %1, 0x989680;\n\t" \
            "@P1 bra.uni WAIT_DONE_%=;\n\t"                                         \
            "bra.uni WAIT_LOOP_%=;\n\t"                                             \
            "WAIT_DONE_%=:\n\t}" :: "r"(_m), "r"(_p) : "memory");                   \
    }                                                                               \
} while (0)

// 1D bulk async copy gmem -> smem, tx-completing on mbar (SASS: UBLKCP).
#define TMA_BULK_G2S(dst, src, bytes, mbar) \
    asm volatile("cp.async.bulk.shared::cta.global.mbarrier::complete_tx::bytes [%0], [%1], %2, [%3];" \
                 :: "r"((uint32_t)(dst)), "l"(src), "r"((uint32_t)(bytes)), "r"((uint32_t)(mbar)) : "memory")

#define TCGEN05_ALLOC(res, n) \
    asm volatile("tcgen05.alloc.cta_group::1.sync.aligned.shared::cta.b32 [%0], %1;" \
                 :: "r"((uint32_t)(res)), "r"((uint32_t)(n)) : "memory")
#define TCGEN05_DEALLOC(addr, n) \
    asm volatile("tcgen05.dealloc.cta_group::1.sync.aligned.b32 %0, %1;" :: "r"(addr), "r"((uint32_t)(n)))
#define TCGEN05_COMMIT(mbar) \
    asm volatile("tcgen05.commit.cta_group::1.mbarrier::arrive::one.shared::cluster.b64 [%0];" \
                 :: "r"((uint32_t)(mbar)) : "memory")
#define TCGEN05_WAIT_LD()  asm volatile("tcgen05.wait::ld.sync.aligned;" ::: "memory")
#define TCGEN05_FENCE_AFTER()  asm volatile("tcgen05.fence::after_thread_sync;" ::: "memory")
#define TCGEN05_FENCE_BEFORE() asm volatile("tcgen05.fence::before_thread_sync;" ::: "memory")

#define TCGEN05_LD_32X32B_X32(r, addr) \
    asm volatile("tcgen05.ld.sync.aligned.32x32b.x32.b32 " \
        "{%0, %1, %2, %3, %4, %5, %6, %7, %8, %9, %10, %11, %12, %13, %14, %15, " \
        " %16, %17, %18, %19, %20, %21, %22, %23, %24, %25, %26, %27, %28, %29, %30, %31}, [%32];" \
        : "=r"((r)[0]),  "=r"((r)[1]),  "=r"((r)[2]),  "=r"((r)[3]), \
          "=r"((r)[4]),  "=r"((r)[5]),  "=r"((r)[6]),  "=r"((r)[7]), \
          "=r"((r)[8]),  "=r"((r)[9]),  "=r"((r)[10]), "=r"((r)[11]), \
          "=r"((r)[12]), "=r"((r)[13]), "=r"((r)[14]), "=r"((r)[15]), \
          "=r"((r)[16]), "=r"((r)[17]), "=r"((r)[18]), "=r"((r)[19]), \
          "=r"((r)[20]), "=r"((r)[21]), "=r"((r)[22]), "=r"((r)[23]), \
          "=r"((r)[24]), "=r"((r)[25]), "=r"((r)[26]), "=r"((r)[27]), \
          "=r"((r)[28]), "=r"((r)[29]), "=r"((r)[30]), "=r"((r)[31]) \
        : "r"(addr))

__device__ __forceinline__ void mma_bf16_ss(uint32_t d, uint64_t a, uint64_t b,
                                            uint32_t idesc, bool acc) {
    uint32_t en = acc ? 1u : 0u;
    asm volatile(
        "{\n\t.reg .pred p;\n\tsetp.ne.u32 p, %5, 0;\n\t"
        "tcgen05.mma.cta_group::1.kind::f16 [%0], %1, %2, %3, {%4, %4, %4, %4}, p;\n\t}"
        :: "r"(d), "l"(a), "l"(b), "r"(idesc), "r"(0u), "r"(en) : "memory");
}
static constexpr uint32_t IDESC_N128 = 0x8200490u;

// Pack 8 fp32 -> 16B hi + 16B lo stores (tile format, matches load/weight path).
__device__ __forceinline__ void store_pack8(uint32_t dsth, uint32_t dstl, const float* v) {
    uint32_t h[4], l[4];
#pragma unroll
    for (int j = 0; j < 4; ++j) {
        uint32_t h0, l0, h1, l1;
        split_bf16(v[2 * j], h0, l0);
        split_bf16(v[2 * j + 1], h1, l1);
        h[j] = h0 | (h1 << 16);
        l[j] = l0 | (l1 << 16);
    }
    asm volatile("st.shared.v4.b32 [%0], {%1,%2,%3,%4};"
                 :: "r"(dsth), "r"(h[0]), "r"(h[1]), "r"(h[2]), "r"(h[3]) : "memory");
    asm volatile("st.shared.v4.b32 [%0], {%1,%2,%3,%4};"
                 :: "r"(dstl), "r"(l[0]), "r"(l[1]), "r"(l[2]), "r"(l[3]) : "memory");
}

// ---------------- flat chunk table: 34 weight chunks across 5 layers ----------------
__device__ __forceinline__ const char* chunk_src(int g, uint32_t& nb) {
    nb = 32768u;
    if (g < 2)  return (const char*)g_w1tile + (size_t)g * 32768;
    if (g < 10) return (const char*)g_w2tile + (size_t)(g - 2) * 32768;
    if (g < 18) return (const char*)g_w3tile + (size_t)(g - 10) * 32768;
    if (g < 26) return (const char*)g_wftile + (size_t)(g - 18) * 32768;
    nb = 16384u;
    return (const char*)g_wdtile + (size_t)(g - 26) * 16384;
}

// Prefetch chunk g into its ring stage (tid 0 only; phase-synchronous waits).
__device__ __forceinline__ void prefetch_chunk(uint32_t smem_base, int g) {
    const int st = g & 1;
    const int uses = g >> 1;                 // prior uses of this stage
    const uint32_t cmb = smem_base + (st ? SM_MB1 : SM_MB0);
    const uint32_t fmb = smem_base + (st ? SM_MBF1 : SM_MBF0);
    if (uses > 0) MBARRIER_WAIT_PARITY(cmb, (uses - 1) & 1);  // stage empty
    uint32_t nb;
    const char* src = chunk_src(g, nb);
    MBARRIER_EXPECT_TX(fmb, nb);
    TMA_BULK_G2S(smem_base + SM_B + st * 32768, src, nb, fmb);
}

// ---------------- one fused layer (prefetch-ahead orchestrator) ----------------
// A tiles resident at SM_A. Weights stream through a 2-stage ring driven by
// tid 0 with prefetch distance 2 across the flat 34-chunk sequence (spanning
// layer boundaries, so next-layer TMA overlaps this layer's epilogue). Only
// tid 0 touches mbarriers; completion is published by __syncthreads.
// HEAD: 0 none, 1 density->sdens, 2 rgb->srgb (no A-tile write).
template <int NCH, int NT, bool RELU, bool ROWBIAS, int HEAD>
__device__ __forceinline__ void run_layer(
    uint32_t smem_base, uint32_t tmem_base,
    const float* __restrict__ bias, const float* __restrict__ rowbias,
    const float* __restrict__ hw, const float* __restrict__ hb,
    int tid, long m0, int& mm, int& pf,
    float* sd, float* sdens, float* srgb)
{
    const int wid = tid >> 5;
    const int lane = tid & 31;

    if (tid == 0) {
        for (int kc = 0; kc < NCH; ++kc) {
            const int st = mm & 1;
            const uint32_t fmb = smem_base + (st ? SM_MBF1 : SM_MBF0);
            const uint32_t cmb = smem_base + (st ? SM_MB1 : SM_MB0);
            // wait for chunk mm's TMA (issued >= 2 chunks ago)
            MBARRIER_WAIT_PARITY(fmb, (mm >> 1) & 1);
            const uint32_t bstage = smem_base + SM_B + st * 32768;
            uint64_t ad = MAKE_SMEM_DESC(smem_base + SM_A + kc * 16384);
#pragma unroll
            for (int nh = 0; nh < NT; ++nh) {
                uint64_t bd = MAKE_SMEM_DESC(bstage + nh * 16384);
                uint32_t d = tmem_base + nh * 128;
#pragma unroll
                for (int ks = 0; ks < 2; ++ks)
                    mma_bf16_ss(d, ad + ks * 2, bd + ks * 2, IDESC_N128, !(kc == 0 && ks == 0));
#pragma unroll
                for (int ks = 0; ks < 2; ++ks)
                    mma_bf16_ss(d, ad + 4 + ks * 2, bd + ks * 2, IDESC_N128, true);
#pragma unroll
                for (int ks = 0; ks < 2; ++ks)
                    mma_bf16_ss(d, ad + ks * 2, bd + 4 + ks * 2, IDESC_N128, true);
            }
            TCGEN05_COMMIT(cmb);
            mm++;
            if (pf < NCHUNKS_TOTAL) { prefetch_chunk(smem_base, pf); pf++; }
        }
        // drain this layer's MMAs (tid 0 stays phase-synchronous)
        const int cs0 = (mm + 1) >> 1, cs1 = mm >> 1;
        if (cs0 > 0) MBARRIER_WAIT_PARITY(smem_base + SM_MB0, (cs0 - 1) & 1);
        if (cs1 > 0) MBARRIER_WAIT_PARITY(smem_base + SM_MB1, (cs1 - 1) & 1);
    } else {
        mm += NCH;          // keep counters consistent (never used for waits here)
        pf = (pf < NCHUNKS_TOTAL) ? min(pf + NCH, NCHUNKS_TOTAL) : pf;
    }

    // publish MMA completion (established by tid 0) to all threads
    __syncthreads();
    TCGEN05_FENCE_AFTER();

    // ---- epilogue (batched TMEM loads: 2 x32 per wait) ----
    const int wg = wid >> 2;
    const int sub = wid & 3;
    if (NT == 2 || wg == 0) {
        const int row = sub * 32 + lane;
        const long grow = m0 + row;
        const float* rbp = ROWBIAS ? (rowbias + (grow >> 6) * (long)(NT * 128)) : nullptr;
        float dpart = 0.0f, a0 = 0.0f, a1 = 0.0f, a2 = 0.0f;
#pragma unroll
        for (int half = 0; half < 2; ++half) {
            uint32_t rA[32], rB[32];
            const int colA = wg * 128 + half * 64;
            const int colB = colA + 32;
            TCGEN05_LD_32X32B_X32(rA, tmem_base + colA);
            TCGEN05_LD_32X32B_X32(rB, tmem_base + colB);
            TCGEN05_WAIT_LD();
#pragma unroll
            for (int q = 0; q < 2; ++q) {
                const uint32_t* regs = q ? rB : rA;
                const int col0 = q ? colB : colA;
                float vals[32];
#pragma unroll
                for (int c = 0; c < 32; ++c) {
                    float v = __uint_as_float(regs[c]) + bias[col0 + c];
                    if (ROWBIAS) v += rbp[col0 + c];
                    if (RELU) v = fmaxf(v, 0.0f);
                    if (HEAD == 1) dpart = fmaf(v, hw[col0 + c], dpart);
                    if (HEAD == 2) {
                        a0 = fmaf(v, hw[(col0 + c) * 3 + 0], a0);
                        a1 = fmaf(v, hw[(col0 + c) * 3 + 1], a1);
                        a2 = fmaf(v, hw[(col0 + c) * 3 + 2], a2);
                    }
                    vals[c] = v;
                }
                if (HEAD != 2) {
                    const int cb = half * 2 + q;
                    uint32_t tb = smem_base + SM_A + (wg * 4 + cb) * 16384;
#pragma unroll
                    for (int u = 0; u < 4; ++u)
                        store_pack8(tb + SMEM_SWIZZLE_128B((uint32_t)(row * 128 + u * 16)),
                                    tb + SMEM_SWIZZLE_128B((uint32_t)(row * 128 + 64 + u * 16)),
                                    vals + u * 8);
                }
            }
        }
        if (HEAD == 1) sd[wg * 128 + row] = dpart;
        if (HEAD == 2) {
            srgb[row * 3 + 0] = 1.0f / (1.0f + __expf(-(a0 + hb[0])));
            srgb[row * 3 + 1] = 1.0f / (1.0f + __expf(-(a1 + hb[1])));
            srgb[row * 3 + 2] = 1.0f / (1.0f + __expf(-(a2 + hb[2])));
        }
    }
    if (HEAD == 1) {
        __syncthreads();
        if (tid < 128) sdens[tid] = sd[tid] + sd[128 + tid] + hb[0];
    }
    TCGEN05_FENCE_BEFORE();
    FENCE_PROXY_ASYNC();
    __syncthreads();
}
#endif  // HAS_TCGEN05

// ---------------- the fused renderer kernel ----------------
__global__ void __launch_bounds__(256)
fused_kernel(const float* __restrict__ xyz,
             const float* __restrict__ b1, const float* __restrict__ b2,
             const float* __restrict__ b3,
             const float* __restrict__ Wsig, const float* __restrict__ bsig,
             const float* __restrict__ bfeat, const float* __restrict__ bdir,
             const float* __restrict__ Wrgb, const float* __restrict__ brgb,
             const float* __restrict__ W1, const float* __restrict__ W2,
             const float* __restrict__ W3, const float* __restrict__ Wfeat,
             const float* __restrict__ Wdir,
             float* __restrict__ out)
{
    extern __shared__ char smem[];
    const int tid = threadIdx.x;
    const long m0 = (long)blockIdx.x * 128;
#if HAS_TCGEN05
    const uint32_t smem_base = smem_to_u32(smem);
    const int wid = tid >> 5;
    float* sd    = reinterpret_cast<float*>(smem + SM_SD);
    float* srgb  = reinterpret_cast<float*>(smem + SM_RGB);
    float* sdens = reinterpret_cast<float*>(smem + SM_DENS);

    if (wid == 0) TCGEN05_ALLOC(smem_base + SM_TM, 256);
    __syncthreads();
    uint32_t tmem_base;
    asm volatile("ld.shared.b32 %0, [%1];" : "=r"(tmem_base) : "r"(smem_base + SM_TM));
    if (tid == 0) {
        MBARRIER_INIT(smem_base + SM_MB0, 1);
        MBARRIER_INIT(smem_base + SM_MB1, 1);
        MBARRIER_INIT(smem_base + SM_MBF0, 1);
        MBARRIER_INIT(smem_base + SM_MBF1, 1);
    }
    __syncthreads();

    // kick off the weight pipeline BEFORE posenc (overlaps TMA with compute)
    if (tid == 0) {
        prefetch_chunk(smem_base, 0);
        prefetch_chunk(smem_base, 1);
    }

    // ---- posenc directly into A tiles 0,1 (K = 64) ----
    {
        int row = tid >> 1;
        int half = tid & 1;
        long grow = m0 + row;
        int ray = (int)(grow >> 6);
        int s = (int)(grow & 63);
        float t = (float)s * (1.0f / 63.0f);
        float sm = NEAR_F * (1.0f - t) + FAR_F * t;
        float p[3];
#pragma unroll
        for (int c = 0; c < 3; ++c)
            p[c] = fmaf(sm, g_vd[ray * 3 + c], xyz[ray * 3 + c]);
        float vals[32];
#pragma unroll
        for (int j = 0; j < 32; ++j) {
            int c = half * 32 + j;
            float val;
            if (c < 3) val = p[c];
            else if (c == 63) val = 0.0f;
            else {
                int q = c - 3, l = q / 6, r = q % 6;
                float ang = p[(r < 3) ? r : r - 3] * (float)(1 << l);
                val = (r < 3) ? sinf(ang) : cosf(ang);
            }
            vals[j] = val;
        }
        uint32_t tb = smem_base + SM_A + half * 16384;
#pragma unroll
        for (int u = 0; u < 4; ++u)
            store_pack8(tb + SMEM_SWIZZLE_128B((uint32_t)(row * 128 + u * 16)),
                        tb + SMEM_SWIZZLE_128B((uint32_t)(row * 128 + 64 + u * 16)),
                        vals + u * 8);
    }
    FENCE_PROXY_ASYNC();
    __syncthreads();

    int mm = 0, pf = 2;
    run_layer<2, 2, true,  false, 0>(smem_base, tmem_base, b1,   nullptr, nullptr, nullptr, tid, m0, mm, pf, sd, sdens, srgb);
    run_layer<8, 2, true,  false, 0>(smem_base, tmem_base, b2,   nullptr, nullptr, nullptr, tid, m0, mm, pf, sd, sdens, srgb);
    run_layer<8, 2, true,  false, 1>(smem_base, tmem_base, b3,   nullptr, Wsig,    bsig,    tid, m0, mm, pf, sd, sdens, srgb);
    run_layer<8, 2, false, false, 0>(smem_base, tmem_base, bfeat,nullptr, nullptr, nullptr, tid, m0, mm, pf, sd, sdens, srgb);
    run_layer<8, 1, true,  true,  2>(smem_base, tmem_base, bdir, g_det,   Wrgb,    brgb,    tid, m0, mm, pf, sd, sdens, srgb);

    // ---- in-kernel volume rendering: this tile = 2 complete rays ----
    if (tid < 2) {
        int ray = (int)(m0 >> 6) + tid;
        float T = 1.0f, r0 = 0.0f, r1 = 0.0f, r2 = 0.0f, depth = 0.0f, asum = 0.0f;
        for (int i = 0; i < NSAMP; ++i) {
            int p = tid * 64 + i;
            float ti = (float)i * (1.0f / 63.0f);
            float sm = NEAR_F * (1.0f - ti) + FAR_F * ti;
            float delta;
            if (i < NSAMP - 1) {
                float tn = (float)(i + 1) * (1.0f / 63.0f);
                delta = (NEAR_F * (1.0f - tn) + FAR_F * tn) - sm;
            } else {
                delta = 1e10f;
            }
            float sigma = fmaxf(sdens[p], 0.0f);
            float alpha = 1.0f - __expf(-sigma * delta);
            float w = T * alpha;
            r0 += w * srgb[p * 3 + 0];
            r1 += w * srgb[p * 3 + 1];
            r2 += w * srgb[p * 3 + 2];
            depth += w * sm;
            asum += w;
            T *= (1.0f - alpha);
        }
        float bk = 1.0f - asum;
        out[ray * 3 + 0] = r0 + bk;
        out[ray * 3 + 1] = r1 + bk;
        out[ray * 3 + 2] = r2 + bk;
        out[R_RAYS * 3 + ray] = depth;
        out[R_RAYS * 4 + ray] = asum;
    }

    __syncthreads();
    if (wid == 0) {
        if (elect_one_pred()) {
            MBARRIER_INVAL(smem_base + SM_MB0);
            MBARRIER_INVAL(smem_base + SM_MB1);
            MBARRIER_INVAL(smem_base + SM_MBF0);
            MBARRIER_INVAL(smem_base + SM_MBF1);
        }
        TCGEN05_DEALLOC(tmem_base, 256);
    }
#else
    // ---------- scalar fallback (non-'a' device passes only; correct, slow) ----------
    float* sdens = reinterpret_cast<float*>(smem);
    float* srgb  = sdens + 128;
    if (tid < 128) {
        long grow = m0 + tid;
        int ray = (int)(grow >> 6);
        int s = (int)(grow & 63);
        float t = (float)s * (1.0f / 63.0f);
        float sm = NEAR_F * (1.0f - t) + FAR_F * t;
        float p[3];
        for (int c = 0; c < 3; ++c)
            p[c] = fmaf(sm, g_vd[ray * 3 + c], xyz[ray * 3 + c]);
        float pe[PE_P];
        pe[0] = p[0]; pe[1] = p[1]; pe[2] = p[2];
        float f = 1.0f;
        for (int l = 0; l < 10; ++l) {
            for (int c = 0; c < 3; ++c) {
                float sn, cs;
                sincosf(p[c] * f, &sn, &cs);
                pe[3 + l * 6 + c] = sn;
                pe[3 + l * 6 + 3 + c] = cs;
            }
            f *= 2.0f;
        }
        float a[256], b[256];
        for (int n = 0; n < 256; ++n) {
            float acc = b1[n];
            for (int k = 0; k < PE_P; ++k) acc = fmaf(pe[k], W1[(size_t)k * 256 + n], acc);
            a[n] = fmaxf(acc, 0.0f);
        }
        for (int n = 0; n < 256; ++n) {
            float acc = b2[n];
            for (int k = 0; k < 256; ++k) acc = fmaf(a[k], W2[(size_t)k * 256 + n], acc);
            b[n] = fmaxf(acc, 0.0f);
        }
        for (int n = 0; n < 256; ++n) {
            float acc = b3[n];
            for (int k = 0; k < 256; ++k) acc = fmaf(b[k], W3[(size_t)k * 256 + n], acc);
            a[n] = fmaxf(acc, 0.0f);
        }
        float dens = bsig[0];
        for (int k = 0; k < 256; ++k) dens = fmaf(a[k], Wsig[k], dens);
        for (int n = 0; n < 256; ++n) {
            float acc = bfeat[n];
            for (int k = 0; k < 256; ++k) acc = fmaf(a[k], Wfeat[(size_t)k * 256 + n], acc);
            b[n] = acc;
        }
        float de[PE_D];
        {
            float vx = g_vd[ray * 3 + 0], vy = g_vd[ray * 3 + 1], vz = g_vd[ray * 3 + 2];
            de[0] = vx; de[1] = vy; de[2] = vz;
            float v3[3] = {vx, vy, vz};
            float ff = 1.0f;
            for (int l = 0; l < 4; ++l) {
                for (int c = 0; c < 3; ++c) {
                    float sn, cs;
                    sincosf(v3[c] * ff, &sn, &cs);
                    de[3 + l * 6 + c] = sn;
                    de[3 + l * 6 + 3 + c] = cs;
                }
                ff *= 2.0f;
            }
        }
        float hd[128];
        for (int n = 0; n < 128; ++n) {
            float acc = bdir[n];
            for (int k = 0; k < 256; ++k) acc = fmaf(b[k], Wdir[(size_t)k * 128 + n], acc);
            for (int k = 0; k < PE_D; ++k) acc = fmaf(de[k], Wdir[(size_t)(256 + k) * 128 + n], acc);
            hd[n] = fmaxf(acc, 0.0f);
        }
        for (int c = 0; c < 3; ++c) {
            float acc = brgb[c];
            for (int k = 0; k < 128; ++k) acc = fmaf(hd[k], Wrgb[k * 3 + c], acc);
            srgb[tid * 3 + c] = 1.0f / (1.0f + expf(-acc));
        }
        sdens[tid] = dens;
    }
    __syncthreads();
    if (tid < 2) {
        int ray = (int)(m0 >> 6) + tid;
        float T = 1.0f, r0 = 0.0f, r1 = 0.0f, r2 = 0.0f, depth = 0.0f, asum = 0.0f;
        for (int i = 0; i < NSAMP; ++i) {
            int p = tid * 64 + i;
            float ti = (float)i * (1.0f / 63.0f);
            float sm = NEAR_F * (1.0f - ti) + FAR_F * ti;
            float delta = (i < NSAMP - 1) ? ((FAR_F - NEAR_F) / 63.0f) : 1e10f;
            float sigma = fmaxf(sdens[p], 0.0f);
            float alpha = 1.0f - expf(-sigma * delta);
            float w = T * alpha;
            r0 += w * srgb[p * 3 + 0];
            r1 += w * srgb[p * 3 + 1];
            r2 += w * srgb[p * 3 + 2];
            depth += w * sm;
            asum += w;
            T *= (1.0f - alpha);
        }
        float bk = 1.0f - asum;
        out[ray * 3 + 0] = r0 + bk;
        out[ray * 3 + 1] = r1 + bk;
        out[ray * 3 + 2] = r2 + bk;
        out[R_RAYS * 3 + ray] = depth;
        out[R_RAYS * 4 + ray] = asum;
    }
#endif
}

// ---------------- host launch ----------------
extern "C" void kernel_launch(void* const* d_in, const int* in_sizes, int n_in,
                              void* d_out, int out_size) {
    const float* xyz      = (const float*)d_in[0];
    const float* viewdirs = (const float*)d_in[1];
    const float* W1   = (const float*)d_in[2];
    const float* b1   = (const float*)d_in[3];
    const float* W2   = (const float*)d_in[4];
    const float* b2   = (const float*)d_in[5];
    const float* W3   = (const float*)d_in[6];
    const float* b3   = (const float*)d_in[7];
    const float* Wsig = (const float*)d_in[8];
    const float* bsig = (const float*)d_in[9];
    const float* Wfeat= (const float*)d_in[10];
    const float* bfeat= (const float*)d_in[11];
    const float* Wdir = (const float*)d_in[12];
    const float* bdir = (const float*)d_in[13];
    const float* Wrgb = (const float*)d_in[14];
    const float* brgb = (const float*)d_in[15];
    float* out = (float*)d_out;

    uint4 *w1t, *w2t, *w3t, *wft, *wdt;
    cudaGetSymbolAddress((void**)&w1t, g_w1tile);
    cudaGetSymbolAddress((void**)&w2t, g_w2tile);
    cudaGetSymbolAddress((void**)&w3t, g_w3tile);
    cudaGetSymbolAddress((void**)&wft, g_wftile);
    cudaGetSymbolAddress((void**)&wdt, g_wdtile);

    cudaFuncSetAttribute(fused_kernel, cudaFuncAttributeMaxDynamicSharedMemorySize, SMEM_TOTAL);

    // ---- prep ----
    prep_rays_kernel<<<R_RAYS / 256, 256>>>(viewdirs);
    de_term_kernel<<<R_RAYS * DHD / 256, 256>>>(Wdir);
    tile_weight_kernel<<<(2 * 2 * 512 + 255) / 256, 256>>>(W1,   w1t, PE_P,  D_HID, 2, 2);
    tile_weight_kernel<<<(8 * 2 * 512 + 255) / 256, 256>>>(W2,   w2t, D_HID, D_HID, 2, 8);
    tile_weight_kernel<<<(8 * 2 * 512 + 255) / 256, 256>>>(W3,   w3t, D_HID, D_HID, 2, 8);
    tile_weight_kernel<<<(8 * 2 * 512 + 255) / 256, 256>>>(Wfeat,wft, D_HID, D_HID, 2, 8);
    tile_weight_kernel<<<(8 * 1 * 512 + 255) / 256, 256>>>(Wdir, wdt, D_HID, DHD,   1, 8);

    // ---- fully fused pipeline: posenc -> 5 MMA layers -> heads -> composite ----
    fused_kernel<<<NPTS / 128, 256, SMEM_TOTAL>>>(
        xyz, b1, b2, b3, Wsig, bsig, bfeat, bdir, Wrgb, brgb,
        W1, W2, W3, Wfeat, Wdir, out);
}